// round 1
// baseline (speedup 1.0000x reference)
#include <cuda_runtime.h>

// Problem constants
#define T      8192
#define NF     128
#define CINP   128
#define BM     64
#define BN     64
#define NSPLIT 4
#define QS     132   // row stride (floats) for Q/K/V smem tiles (bank-conflict pad)
#define SS     68    // row stride for S/P tile
#define WS     68    // row stride for W tile (projection)
#define QSCALE 0.08838834764831845f  // 1/sqrt(128)

// Scratch (no cudaMalloc allowed): Q,K,V + split partials
__device__ float g_Q[T * NF];
__device__ float g_K[T * NF];
__device__ float g_V[T * NF];
__device__ float g_O[NSPLIT * T * NF];
__device__ float g_M[NSPLIT * T];
__device__ float g_L[NSPLIT * T];

__device__ __forceinline__ float neg_inf() { return __int_as_float(0xff800000u); }

// ---------------------------------------------------------------------------
// Kernel 1: QKV projection.  qkv = x @ W + b; Q gets 1/sqrt(NF) folded in;
// V rows < n_padd zeroed.  Tiles: 64 rows x 64 cols, K = 128.
// ---------------------------------------------------------------------------
__global__ void __launch_bounds__(256) proj_kernel(
    const float* __restrict__ x, const float* __restrict__ W,
    const float* __restrict__ b, const int* __restrict__ npadd_p) {
  extern __shared__ float sm[];
  float* xs = sm;               // [64][QS]
  float* ws = sm + BM * QS;     // [128][WS]
  const int tid = threadIdx.x;
  const int tx = tid & 15, ty = tid >> 4;
  const int row0 = blockIdx.x * BM;
  const int col0 = blockIdx.y * 64;

#pragma unroll
  for (int it = 0; it < 8; ++it) {            // 64x128 floats = 2048 float4
    int idx = tid + it * 256;
    int r = idx >> 5, c4 = idx & 31;
    *(float4*)&xs[r * QS + c4 * 4] =
        *(const float4*)&x[(row0 + r) * CINP + c4 * 4];
  }
#pragma unroll
  for (int it = 0; it < 8; ++it) {            // 128x64 floats = 2048 float4
    int idx = tid + it * 256;
    int r = idx >> 4, c4 = idx & 15;
    *(float4*)&ws[r * WS + c4 * 4] =
        *(const float4*)&W[r * (3 * NF) + col0 + c4 * 4];
  }
  __syncthreads();

  float acc[4][4] = {};
#pragma unroll 4
  for (int k4 = 0; k4 < 32; ++k4) {
    float xr[4][4];
#pragma unroll
    for (int i = 0; i < 4; ++i) {
      float4 t = *(const float4*)&xs[(ty * 4 + i) * QS + k4 * 4];
      xr[i][0] = t.x; xr[i][1] = t.y; xr[i][2] = t.z; xr[i][3] = t.w;
    }
#pragma unroll
    for (int kk = 0; kk < 4; ++kk) {
      int k = k4 * 4 + kk;
      float wv[4];
#pragma unroll
      for (int j = 0; j < 4; ++j) wv[j] = ws[k * WS + tx + 16 * j];
#pragma unroll
      for (int i = 0; i < 4; ++i)
#pragma unroll
        for (int j = 0; j < 4; ++j)
          acc[i][j] = fmaf(xr[i][kk], wv[j], acc[i][j]);
    }
  }

  const int npadd = *npadd_p;
#pragma unroll
  for (int j = 0; j < 4; ++j) {
    int gc = col0 + tx + 16 * j;
    float bias = b[gc];
#pragma unroll
    for (int i = 0; i < 4; ++i) {
      int gr = row0 + ty * 4 + i;
      float v = acc[i][j] + bias;
      if (gc < NF) {
        g_Q[gr * NF + gc] = v * QSCALE;
      } else if (gc < 2 * NF) {
        g_K[gr * NF + (gc - NF)] = v;
      } else {
        g_V[gr * NF + (gc - 2 * NF)] = (gr >= npadd) ? v : 0.0f;
      }
    }
  }
}

// ---------------------------------------------------------------------------
// Kernel 2: causal flash attention, split-KV (4 splits per 64-row query tile).
// Block (qt, sp): query rows [qt*64, qt*64+64), key tiles [kt0, kt1).
// Writes unnormalized O, running max M and sum L per row per split.
// ---------------------------------------------------------------------------
__global__ void __launch_bounds__(256) attn_kernel(const int* __restrict__ npadd_p) {
  extern __shared__ float sm[];
  float* Qs = sm;               // [64][QS]
  float* Ks = Qs + BM * QS;     // [64][QS]
  float* Vs = Ks + BN * QS;     // [64][QS]
  float* Ss = Vs + BN * QS;     // [64][SS]
  __shared__ float sm_m[BM], sm_l[BM], sm_alpha[BM], red[256];

  const int tid = threadIdx.x;
  const int tx = tid & 15, ty = tid >> 4;
  const int qt = (gridDim.x - 1) - blockIdx.x;   // big blocks launch first
  const int sp = blockIdx.y;
  const int npadd = *npadd_p;
  const int qrow0 = qt * BM;
  const int ntiles = qt + 1;
  const int kt0 = (sp * ntiles) / NSPLIT;
  const int kt1 = ((sp + 1) * ntiles) / NSPLIT;

#pragma unroll
  for (int it = 0; it < 8; ++it) {
    int idx = tid + it * 256;
    int r = idx >> 5, c4 = idx & 31;
    *(float4*)&Qs[r * QS + c4 * 4] =
        *(const float4*)&g_Q[(qrow0 + r) * NF + c4 * 4];
  }
  if (tid < BM) { sm_m[tid] = neg_inf(); sm_l[tid] = 0.0f; }
  float acc[4][8];
#pragma unroll
  for (int i = 0; i < 4; ++i)
#pragma unroll
    for (int c = 0; c < 8; ++c) acc[i][c] = 0.0f;
  __syncthreads();

  const int srow = tid & 63;   // row handled in stat/exp passes
  const int sg = tid >> 6;     // 16-col group

  for (int kt = kt0; kt < kt1; ++kt) {
    const int kbase = kt * BN;

    // ---- load K, V tiles ----
#pragma unroll
    for (int it = 0; it < 8; ++it) {
      int idx = tid + it * 256;
      int r = idx >> 5, c4 = idx & 31;
      *(float4*)&Ks[r * QS + c4 * 4] =
          *(const float4*)&g_K[(kbase + r) * NF + c4 * 4];
      *(float4*)&Vs[r * QS + c4 * 4] =
          *(const float4*)&g_V[(kbase + r) * NF + c4 * 4];
    }
    __syncthreads();

    // ---- stage A: S = Q K^T (64x64, k=128) ----
    float sacc[4][4] = {};
#pragma unroll 8
    for (int k4 = 0; k4 < 32; ++k4) {
      float qr[4][4], kr[4][4];
#pragma unroll
      for (int i = 0; i < 4; ++i) {
        float4 t = *(const float4*)&Qs[(ty * 4 + i) * QS + k4 * 4];
        qr[i][0] = t.x; qr[i][1] = t.y; qr[i][2] = t.z; qr[i][3] = t.w;
      }
#pragma unroll
      for (int j = 0; j < 4; ++j) {
        float4 t = *(const float4*)&Ks[(tx + 16 * j) * QS + k4 * 4];
        kr[j][0] = t.x; kr[j][1] = t.y; kr[j][2] = t.z; kr[j][3] = t.w;
      }
#pragma unroll
      for (int kk = 0; kk < 4; ++kk)
#pragma unroll
        for (int i = 0; i < 4; ++i)
#pragma unroll
          for (int j = 0; j < 4; ++j)
            sacc[i][j] = fmaf(qr[i][kk], kr[j][kk], sacc[i][j]);
    }
#pragma unroll
    for (int i = 0; i < 4; ++i)
#pragma unroll
      for (int j = 0; j < 4; ++j)
        Ss[(ty * 4 + i) * SS + tx + 16 * j] = sacc[i][j];
    __syncthreads();

    // ---- row max (with causal / padding mask) ----
    const bool need_mask = (kt == qt) || (kbase < npadd) || (qrow0 < npadd);
    float vals[16];
    float m16 = neg_inf();
    const int gi = qrow0 + srow;
#pragma unroll
    for (int c4 = 0; c4 < 4; ++c4) {
      float4 t = *(const float4*)&Ss[srow * SS + sg * 16 + c4 * 4];
      float tv[4] = {t.x, t.y, t.z, t.w};
#pragma unroll
      for (int e = 0; e < 4; ++e) {
        if (need_mask) {
          int gj = kbase + sg * 16 + c4 * 4 + e;
          bool ok = (gj <= gi) && (gj >= npadd) && (gi >= npadd);
          if (!ok) tv[e] = neg_inf();
        }
        vals[c4 * 4 + e] = tv[e];
        m16 = fmaxf(m16, tv[e]);
      }
    }
    red[sg * 64 + srow] = m16;
    __syncthreads();
    if (tid < BM) {
      float mn = fmaxf(fmaxf(red[tid], red[64 + tid]),
                       fmaxf(red[128 + tid], red[192 + tid]));
      float mold = sm_m[tid];
      float mnew = fmaxf(mold, mn);
      float a = (mnew == neg_inf()) ? 1.0f : __expf(mold - mnew);
      sm_alpha[tid] = a;
      sm_m[tid] = mnew;
    }
    __syncthreads();

    // ---- P = exp(S - m), row sums ----
    const float mrow = sm_m[srow];
    const bool dead = (mrow == neg_inf());
    float s16 = 0.0f;
#pragma unroll
    for (int c4 = 0; c4 < 4; ++c4) {
      float pv[4];
#pragma unroll
      for (int e = 0; e < 4; ++e) {
        float pe = dead ? 0.0f : __expf(vals[c4 * 4 + e] - mrow);
        pv[e] = pe;
        s16 += pe;
      }
      float4 p; p.x = pv[0]; p.y = pv[1]; p.z = pv[2]; p.w = pv[3];
      *(float4*)&Ss[srow * SS + sg * 16 + c4 * 4] = p;
    }
    red[sg * 64 + srow] = s16;
    __syncthreads();
    if (tid < BM) {
      float rs = red[tid] + red[64 + tid] + red[128 + tid] + red[192 + tid];
      sm_l[tid] = sm_l[tid] * sm_alpha[tid] + rs;
    }

    // ---- stage B: acc = acc*alpha + P @ V ----
#pragma unroll
    for (int i = 0; i < 4; ++i) {
      float a = sm_alpha[ty * 4 + i];
#pragma unroll
      for (int c = 0; c < 8; ++c) acc[i][c] *= a;
    }
#pragma unroll 4
    for (int j4 = 0; j4 < 16; ++j4) {
      float pr[4][4];
#pragma unroll
      for (int i = 0; i < 4; ++i) {
        float4 t = *(const float4*)&Ss[(ty * 4 + i) * SS + j4 * 4];
        pr[i][0] = t.x; pr[i][1] = t.y; pr[i][2] = t.z; pr[i][3] = t.w;
      }
#pragma unroll
      for (int jj = 0; jj < 4; ++jj) {
        int vr = j4 * 4 + jj;
        float vv[8];
#pragma unroll
        for (int g2 = 0; g2 < 4; ++g2) {
          float2 t = *(const float2*)&Vs[vr * QS + g2 * 32 + tx * 2];
          vv[g2 * 2] = t.x; vv[g2 * 2 + 1] = t.y;
        }
#pragma unroll
        for (int i = 0; i < 4; ++i) {
          float p = pr[i][jj];
#pragma unroll
          for (int c = 0; c < 8; ++c)
            acc[i][c] = fmaf(p, vv[c], acc[i][c]);
        }
      }
    }
    __syncthreads();
  }

  // ---- write split partials (unnormalized O, plus m and l) ----
#pragma unroll
  for (int i = 0; i < 4; ++i) {
    int gr = qrow0 + ty * 4 + i;
#pragma unroll
    for (int g2 = 0; g2 < 4; ++g2) {
      float2 t = make_float2(acc[i][g2 * 2], acc[i][g2 * 2 + 1]);
      *(float2*)&g_O[(sp * T + gr) * NF + g2 * 32 + tx * 2] = t;
    }
  }
  if (tid < BM) {
    g_M[sp * T + qrow0 + tid] = sm_m[tid];
    g_L[sp * T + qrow0 + tid] = sm_l[tid];
  }
}

// ---------------------------------------------------------------------------
// Kernel 3: combine splits.  out[t][c] = sum_s w_s*O_s / sum_s w_s*l_s,
// w_s = exp(m_s - max_s m_s).  Two rows per 256-thread block.
// ---------------------------------------------------------------------------
__global__ void __launch_bounds__(256) combine_kernel(float* __restrict__ out) {
  const int tid = threadIdx.x;
  const int t = blockIdx.x * 2 + (tid >> 7);
  const int c = tid & 127;
  float m[NSPLIT], l[NSPLIT];
  float mx = neg_inf();
#pragma unroll
  for (int s = 0; s < NSPLIT; ++s) {
    m[s] = g_M[s * T + t];
    l[s] = g_L[s * T + t];
    mx = fmaxf(mx, m[s]);
  }
  if (mx == neg_inf()) { out[t * NF + c] = 0.0f; return; }
  float den = 0.0f, num = 0.0f;
#pragma unroll
  for (int s = 0; s < NSPLIT; ++s) {
    float w = (m[s] == neg_inf()) ? 0.0f : __expf(m[s] - mx);
    den += w * l[s];
    num = fmaf(w, g_O[(s * T + t) * NF + c], num);
  }
  out[t * NF + c] = num / den;
}

// ---------------------------------------------------------------------------
extern "C" void kernel_launch(void* const* d_in, const int* in_sizes, int n_in,
                              void* d_out, int out_size) {
  const float* x = (const float*)d_in[0];
  const float* W = (const float*)d_in[1];
  const float* b = (const float*)d_in[2];
  const int* npadd = (const int*)d_in[3];
  float* out = (float*)d_out;

  constexpr int PROJ_SMEM = (BM * QS + 128 * WS) * (int)sizeof(float);      // ~67 KB
  constexpr int ATTN_SMEM = (3 * BM * QS + BM * SS) * (int)sizeof(float);   // ~116 KB
  cudaFuncSetAttribute(proj_kernel, cudaFuncAttributeMaxDynamicSharedMemorySize, PROJ_SMEM);
  cudaFuncSetAttribute(attn_kernel, cudaFuncAttributeMaxDynamicSharedMemorySize, ATTN_SMEM);

  proj_kernel<<<dim3(T / BM, (3 * NF) / 64), 256, PROJ_SMEM>>>(x, W, b, npadd);
  attn_kernel<<<dim3(T / BM, NSPLIT), 256, ATTN_SMEM>>>(npadd);
  combine_kernel<<<T / 2, 256>>>(out);
}

// round 3
// speedup vs baseline: 2.7052x; 2.7052x over previous
#include <cuda_runtime.h>
#include <cstdint>

// Problem constants
#define T      8192
#define NF     128
#define CINP   128
#define QSCALE 0.08838834764831845f  // 1/sqrt(128)
#define NSPLIT_MAX 8

// Attention tiling
#define BM 128          // query rows per CTA
#define BN 64           // keys per inner tile
#define NKT 16          // key tiles (of 64) per chunk -> 1024 keys/chunk
#define KST 132         // K smem row stride (floats): B-frag conflict-free
#define VST 136         // V smem row stride: B-frag conflict-free
#define PST 68          // P smem row stride: A-frag conflict-free
#define QST 132         // Q staging stride

// Scratch (no cudaMalloc allowed)
__device__ float g_Q[T * NF];
__device__ float g_K[T * NF];
__device__ float g_V[T * NF];
__device__ float g_O[NSPLIT_MAX * T * NF];
__device__ float g_M[NSPLIT_MAX * T];
__device__ float g_L[NSPLIT_MAX * T];

__device__ __forceinline__ float neg_inf() { return __int_as_float(0xff800000u); }

__device__ __forceinline__ uint32_t f2tf32(float f) {
  uint32_t u;
  asm("cvt.rna.tf32.f32 %0, %1;" : "=r"(u) : "f"(f));
  return u;
}
__device__ __forceinline__ float tf32f(float f) {
  return __uint_as_float(f2tf32(f));
}

// D += A(16x8) * B(8x8), tf32 inputs, f32 accum
__device__ __forceinline__ void mma_tf32(float* d, const uint32_t* a,
                                         const uint32_t* b) {
  asm volatile(
      "mma.sync.aligned.m16n8k8.row.col.f32.tf32.tf32.f32 "
      "{%0,%1,%2,%3}, {%4,%5,%6,%7}, {%8,%9}, {%0,%1,%2,%3};\n"
      : "+f"(d[0]), "+f"(d[1]), "+f"(d[2]), "+f"(d[3])
      : "r"(a[0]), "r"(a[1]), "r"(a[2]), "r"(a[3]), "r"(b[0]), "r"(b[1]));
}

// ---------------------------------------------------------------------------
// Kernel 1: QKV projection (unchanged — 32us)
// ---------------------------------------------------------------------------
#define PBM 64
#define PQS 132
#define PWS 68
__global__ void __launch_bounds__(256) proj_kernel(
    const float* __restrict__ x, const float* __restrict__ W,
    const float* __restrict__ b, const int* __restrict__ npadd_p) {
  extern __shared__ float sm[];
  float* xs = sm;
  float* ws = sm + PBM * PQS;
  const int tid = threadIdx.x;
  const int tx = tid & 15, ty = tid >> 4;
  const int row0 = blockIdx.x * PBM;
  const int col0 = blockIdx.y * 64;

#pragma unroll
  for (int it = 0; it < 8; ++it) {
    int idx = tid + it * 256;
    int r = idx >> 5, c4 = idx & 31;
    *(float4*)&xs[r * PQS + c4 * 4] =
        *(const float4*)&x[(row0 + r) * CINP + c4 * 4];
  }
#pragma unroll
  for (int it = 0; it < 8; ++it) {
    int idx = tid + it * 256;
    int r = idx >> 4, c4 = idx & 15;
    *(float4*)&ws[r * PWS + c4 * 4] =
        *(const float4*)&W[r * (3 * NF) + col0 + c4 * 4];
  }
  __syncthreads();

  float acc[4][4] = {};
#pragma unroll 4
  for (int k4 = 0; k4 < 32; ++k4) {
    float xr[4][4];
#pragma unroll
    for (int i = 0; i < 4; ++i) {
      float4 t = *(const float4*)&xs[(ty * 4 + i) * PQS + k4 * 4];
      xr[i][0] = t.x; xr[i][1] = t.y; xr[i][2] = t.z; xr[i][3] = t.w;
    }
#pragma unroll
    for (int kk = 0; kk < 4; ++kk) {
      int k = k4 * 4 + kk;
      float wv[4];
#pragma unroll
      for (int j = 0; j < 4; ++j) wv[j] = ws[k * PWS + tx + 16 * j];
#pragma unroll
      for (int i = 0; i < 4; ++i)
#pragma unroll
        for (int j = 0; j < 4; ++j)
          acc[i][j] = fmaf(xr[i][kk], wv[j], acc[i][j]);
    }
  }

  const int npadd = *npadd_p;
#pragma unroll
  for (int j = 0; j < 4; ++j) {
    int gc = col0 + tx + 16 * j;
    float bias = b[gc];
#pragma unroll
    for (int i = 0; i < 4; ++i) {
      int gr = row0 + ty * 4 + i;
      float v = acc[i][j] + bias;
      if (gc < NF) {
        g_Q[gr * NF + gc] = v * QSCALE;
      } else if (gc < 2 * NF) {
        g_K[gr * NF + (gc - NF)] = v;
      } else {
        g_V[gr * NF + (gc - 2 * NF)] = (gr >= npadd) ? v : 0.0f;
      }
    }
  }
}

// ---------------------------------------------------------------------------
// Kernel 2: flash attention via mma.sync tf32.
// CTA = (q tile of 128 rows, chunk of <=16 key tiles of 64).
// 8 warps; warp w owns rows 16w..16w+15 end-to-end (warp-local softmax).
// ---------------------------------------------------------------------------
__global__ void __launch_bounds__(256, 1) attn_kernel(const int* __restrict__ npadd_p) {
  extern __shared__ float sm[];
  float* Ks = sm;                       // [64][KST]
  float* Vs = sm + BN * KST;            // [64][VST]
  float* Ps = sm + BN * KST + BN * VST; // 8 warps x [16][PST]
  float* Qs = sm;                       // staging, overlaps Ks/Vs (used first)

  const int tid = threadIdx.x;
  const int lane = tid & 31;
  const int w = tid >> 5;
  const int tq = lane >> 2;   // 0..7
  const int tr = lane & 3;    // 0..3

  const int qt = 63 - blockIdx.x;       // big tiles first
  const int ch = blockIdx.y;
  const int kcount = 2 * (qt + 1);      // total 64-key tiles for this q tile
  const int nch = (kcount + NKT - 1) / NKT;
  if (ch >= nch) return;
  const int k0 = ch * NKT;
  const int k1 = (k0 + NKT < kcount) ? (k0 + NKT) : kcount;
  const int npadd = *npadd_p;
  const int qrow0 = qt * BM;

  // ---- stage Q, extract A-fragments into registers ----
#pragma unroll
  for (int it = 0; it < 16; ++it) {
    int idx = tid + it * 256;
    int r = idx >> 5, c4 = idx & 31;
    float4 v = *(const float4*)&g_Q[(qrow0 + r) * NF + c4 * 4];
    float* d = &Qs[r * QST + c4 * 4];
    d[0] = tf32f(v.x); d[1] = tf32f(v.y); d[2] = tf32f(v.z); d[3] = tf32f(v.w);
  }
  __syncthreads();

  uint32_t qa[16][4];
  {
    const float* q0 = &Qs[(16 * w + tq) * QST];
    const float* q1 = &Qs[(16 * w + tq + 8) * QST];
#pragma unroll
    for (int kk = 0; kk < 16; ++kk) {
      qa[kk][0] = __float_as_uint(q0[kk * 8 + tr]);
      qa[kk][1] = __float_as_uint(q1[kk * 8 + tr]);
      qa[kk][2] = __float_as_uint(q0[kk * 8 + tr + 4]);
      qa[kk][3] = __float_as_uint(q1[kk * 8 + tr + 4]);
    }
  }

  const int r0g = qrow0 + 16 * w + tq;
  const int r1g = r0g + 8;
  float m0 = neg_inf(), m1 = neg_inf(), l0 = 0.0f, l1 = 0.0f;
  float o[16][4];
#pragma unroll
  for (int n = 0; n < 16; ++n)
#pragma unroll
    for (int i = 0; i < 4; ++i) o[n][i] = 0.0f;

  float* pw = Ps + w * 16 * PST;

  for (int kt = k0; kt < k1; ++kt) {
    const int kbase = kt * BN;
    __syncthreads();  // prior iteration (or Q staging) done with smem

    // ---- load K, V tiles (tf32-converted) ----
#pragma unroll
    for (int it = 0; it < 8; ++it) {
      int idx = tid + it * 256;
      int r = idx >> 5, c4 = idx & 31;
      float4 kv = *(const float4*)&g_K[(kbase + r) * NF + c4 * 4];
      float* kd = &Ks[r * KST + c4 * 4];
      kd[0] = tf32f(kv.x); kd[1] = tf32f(kv.y); kd[2] = tf32f(kv.z); kd[3] = tf32f(kv.w);
      float4 vv = *(const float4*)&g_V[(kbase + r) * NF + c4 * 4];
      float* vd = &Vs[r * VST + c4 * 4];
      vd[0] = tf32f(vv.x); vd[1] = tf32f(vv.y); vd[2] = tf32f(vv.z); vd[3] = tf32f(vv.w);
    }
    __syncthreads();

    // ---- S = Q @ K^T : warp computes 16x64 ----
    float s[8][4];
#pragma unroll
    for (int n = 0; n < 8; ++n)
#pragma unroll
      for (int i = 0; i < 4; ++i) s[n][i] = 0.0f;

#pragma unroll
    for (int kk = 0; kk < 16; ++kk) {
#pragma unroll
      for (int nt = 0; nt < 8; ++nt) {
        uint32_t bb[2];
        const float* kp = &Ks[(nt * 8 + tq) * KST + kk * 8 + tr];
        bb[0] = __float_as_uint(kp[0]);
        bb[1] = __float_as_uint(kp[4]);
        mma_tf32(s[nt], qa[kk], bb);
      }
    }

    // ---- mask ----
    const bool needmask = (kbase + BN > qrow0) || (kbase < npadd) || (qrow0 < npadd);
    if (needmask) {
#pragma unroll
      for (int nt = 0; nt < 8; ++nt) {
        int j0 = kbase + nt * 8 + 2 * tr;
        int j1 = j0 + 1;
        if (j0 > r0g || j0 < npadd || r0g < npadd) s[nt][0] = neg_inf();
        if (j1 > r0g || j1 < npadd || r0g < npadd) s[nt][1] = neg_inf();
        if (j0 > r1g || j0 < npadd || r1g < npadd) s[nt][2] = neg_inf();
        if (j1 > r1g || j1 < npadd || r1g < npadd) s[nt][3] = neg_inf();
      }
    }

    // ---- warp-local online softmax (rows r0g, r1g) ----
    float mx0 = neg_inf(), mx1 = neg_inf();
#pragma unroll
    for (int nt = 0; nt < 8; ++nt) {
      mx0 = fmaxf(mx0, fmaxf(s[nt][0], s[nt][1]));
      mx1 = fmaxf(mx1, fmaxf(s[nt][2], s[nt][3]));
    }
    mx0 = fmaxf(mx0, __shfl_xor_sync(0xffffffffu, mx0, 1));
    mx0 = fmaxf(mx0, __shfl_xor_sync(0xffffffffu, mx0, 2));
    mx1 = fmaxf(mx1, __shfl_xor_sync(0xffffffffu, mx1, 1));
    mx1 = fmaxf(mx1, __shfl_xor_sync(0xffffffffu, mx1, 2));

    float mn0 = fmaxf(m0, mx0);
    float mn1 = fmaxf(m1, mx1);
    float a0 = (mn0 == neg_inf()) ? 1.0f : __expf(m0 - mn0);
    float a1 = (mn1 == neg_inf()) ? 1.0f : __expf(m1 - mn1);
    m0 = mn0; m1 = mn1;
    const bool dead0 = (mn0 == neg_inf());
    const bool dead1 = (mn1 == neg_inf());

#pragma unroll
    for (int n = 0; n < 16; ++n) {
      o[n][0] *= a0; o[n][1] *= a0;
      o[n][2] *= a1; o[n][3] *= a1;
    }

    float sum0 = 0.0f, sum1 = 0.0f;
#pragma unroll
    for (int nt = 0; nt < 8; ++nt) {
      float p0 = dead0 ? 0.0f : __expf(s[nt][0] - mn0);
      float p1 = dead0 ? 0.0f : __expf(s[nt][1] - mn0);
      float p2 = dead1 ? 0.0f : __expf(s[nt][2] - mn1);
      float p3 = dead1 ? 0.0f : __expf(s[nt][3] - mn1);
      sum0 += p0 + p1; sum1 += p2 + p3;
      s[nt][0] = p0; s[nt][1] = p1; s[nt][2] = p2; s[nt][3] = p3;
    }
    sum0 += __shfl_xor_sync(0xffffffffu, sum0, 1);
    sum0 += __shfl_xor_sync(0xffffffffu, sum0, 2);
    sum1 += __shfl_xor_sync(0xffffffffu, sum1, 1);
    sum1 += __shfl_xor_sync(0xffffffffu, sum1, 2);
    l0 = l0 * a0 + sum0;
    l1 = l1 * a1 + sum1;

    // ---- P: C-fragment -> smem -> A-fragment (per-warp patch) ----
#pragma unroll
    for (int nt = 0; nt < 8; ++nt) {
      *(float2*)&pw[tq * PST + nt * 8 + 2 * tr] =
          make_float2(tf32f(s[nt][0]), tf32f(s[nt][1]));
      *(float2*)&pw[(tq + 8) * PST + nt * 8 + 2 * tr] =
          make_float2(tf32f(s[nt][2]), tf32f(s[nt][3]));
    }
    __syncwarp();

    // ---- O += P @ V ----
#pragma unroll
    for (int kt8 = 0; kt8 < 8; ++kt8) {
      uint32_t pa[4];
      pa[0] = __float_as_uint(pw[tq * PST + kt8 * 8 + tr]);
      pa[1] = __float_as_uint(pw[(tq + 8) * PST + kt8 * 8 + tr]);
      pa[2] = __float_as_uint(pw[tq * PST + kt8 * 8 + tr + 4]);
      pa[3] = __float_as_uint(pw[(tq + 8) * PST + kt8 * 8 + tr + 4]);
#pragma unroll
      for (int nt2 = 0; nt2 < 16; ++nt2) {
        uint32_t bb[2];
        const float* vp = &Vs[(kt8 * 8 + tr) * VST + nt2 * 8 + tq];
        bb[0] = __float_as_uint(vp[0]);
        bb[1] = __float_as_uint(vp[4 * VST]);
        mma_tf32(o[nt2], pa, bb);
      }
    }
    __syncwarp();
  }

  // ---- write split partials (unnormalized) ----
  float* ob0 = &g_O[((size_t)ch * T + r0g) * NF];
  float* ob1 = &g_O[((size_t)ch * T + r1g) * NF];
#pragma unroll
  for (int nt2 = 0; nt2 < 16; ++nt2) {
    int c = nt2 * 8 + 2 * tr;
    *(float2*)&ob0[c] = make_float2(o[nt2][0], o[nt2][1]);
    *(float2*)&ob1[c] = make_float2(o[nt2][2], o[nt2][3]);
  }
  if (tr == 0) {
    g_M[ch * T + r0g] = m0; g_M[ch * T + r1g] = m1;
    g_L[ch * T + r0g] = l0; g_L[ch * T + r1g] = l1;
  }
}

// ---------------------------------------------------------------------------
// Kernel 3: combine split partials.
// ---------------------------------------------------------------------------
__global__ void __launch_bounds__(256) combine_kernel(float* __restrict__ out) {
  const int tid = threadIdx.x;
  const int t = blockIdx.x * 2 + (tid >> 7);
  const int c = tid & 127;
  const int qt = t >> 7;
  const int nch = (qt + 8) / 8;   // = ceil(2*(qt+1)/16)

  float m[NSPLIT_MAX], l[NSPLIT_MAX];
  float mx = neg_inf();
  for (int s = 0; s < nch; ++s) {
    m[s] = g_M[s * T + t];
    l[s] = g_L[s * T + t];
    mx = fmaxf(mx, m[s]);
  }
  if (mx == neg_inf()) { out[t * NF + c] = 0.0f; return; }
  float den = 0.0f, num = 0.0f;
  for (int s = 0; s < nch; ++s) {
    float wgt = (m[s] == neg_inf()) ? 0.0f : __expf(m[s] - mx);
    den += wgt * l[s];
    num = fmaf(wgt, g_O[((size_t)s * T + t) * NF + c], num);
  }
  out[t * NF + c] = num / den;
}

// ---------------------------------------------------------------------------
extern "C" void kernel_launch(void* const* d_in, const int* in_sizes, int n_in,
                              void* d_out, int out_size) {
  const float* x = (const float*)d_in[0];
  const float* W = (const float*)d_in[1];
  const float* b = (const float*)d_in[2];
  const int* npadd = (const int*)d_in[3];
  float* out = (float*)d_out;

  constexpr int PROJ_SMEM = (PBM * PQS + 128 * PWS) * (int)sizeof(float);
  constexpr int ATTN_SMEM =
      (BN * KST + BN * VST + 8 * 16 * PST) * (int)sizeof(float);  // ~101 KB
  cudaFuncSetAttribute(proj_kernel, cudaFuncAttributeMaxDynamicSharedMemorySize, PROJ_SMEM);
  cudaFuncSetAttribute(attn_kernel, cudaFuncAttributeMaxDynamicSharedMemorySize, ATTN_SMEM);

  proj_kernel<<<dim3(T / PBM, (3 * NF) / 64), 256, PROJ_SMEM>>>(x, W, b, npadd);
  attn_kernel<<<dim3(64, NSPLIT_MAX), 256, ATTN_SMEM>>>(npadd);
  combine_kernel<<<T / 2, 256>>>(out);
}

// round 4
// speedup vs baseline: 3.0477x; 1.1266x over previous
#include <cuda_runtime.h>
#include <cstdint>

// Problem constants
#define T      8192
#define NF     128
#define CINP   128
#define QSCALE 0.08838834764831845f  // 1/sqrt(128)
#define NSPLIT_MAX 8

// Attention tiling
#define BM 128          // query rows per CTA
#define BN 64           // keys per inner tile
#define NKT 16          // key tiles (of 64) per chunk -> 1024 keys/chunk
#define KST 136         // K smem row stride (floats): packed float2 reads conflict-free
#define VST 136         // V smem row stride: scalar B-frag reads conflict-free
#define PST 68          // P smem row stride
#define QST 132         // Q staging stride

// Scratch (no cudaMalloc allowed).  g_Q/g_K/g_V hold tf32-pre-rounded values;
// g_K additionally has columns pair-packed within each 8-group.
__device__ float g_Q[T * NF];
__device__ float g_K[T * NF];
__device__ float g_V[T * NF];
__device__ float g_O[NSPLIT_MAX * T * NF];
__device__ float g_M[NSPLIT_MAX * T];
__device__ float g_L[NSPLIT_MAX * T];

__device__ __forceinline__ float neg_inf() { return __int_as_float(0xff800000u); }

__device__ __forceinline__ uint32_t f2tf32(float f) {
  uint32_t u;
  asm("cvt.rna.tf32.f32 %0, %1;" : "=r"(u) : "f"(f));
  return u;
}
__device__ __forceinline__ float tf32f(float f) {
  return __uint_as_float(f2tf32(f));
}

// packed position of column c within its 8-group: [0,4,1,5,2,6,3,7]
__device__ __forceinline__ int packc(int c) {
  return (c & ~7) | (2 * (c & 3) + ((c >> 2) & 1));
}

// D += A(16x8) * B(8x8), tf32 inputs, f32 accum
__device__ __forceinline__ void mma_tf32(float* d, const uint32_t* a,
                                         const uint32_t* b) {
  asm volatile(
      "mma.sync.aligned.m16n8k8.row.col.f32.tf32.tf32.f32 "
      "{%0,%1,%2,%3}, {%4,%5,%6,%7}, {%8,%9}, {%0,%1,%2,%3};\n"
      : "+f"(d[0]), "+f"(d[1]), "+f"(d[2]), "+f"(d[3])
      : "r"(a[0]), "r"(a[1]), "r"(a[2]), "r"(a[3]), "r"(b[0]), "r"(b[1]));
}

__device__ __forceinline__ uint32_t smem_u32(const void* p) {
  uint32_t a;
  asm("{ .reg .u64 t; cvta.to.shared.u64 t, %1; cvt.u32.u64 %0, t; }"
      : "=r"(a) : "l"(p));
  return a;
}
__device__ __forceinline__ void cp16(uint32_t daddr, const void* src) {
  asm volatile("cp.async.cg.shared.global [%0], [%1], 16;"
               :: "r"(daddr), "l"(src));
}

// ---------------------------------------------------------------------------
// Kernel 1: QKV projection via mma.sync tf32, 2-term split (x_hi + x_lo).
// CTA = (128 rows, 64 out-cols).  grid (64, 6); by>>1 = section (q/k/v).
// Outputs pre-rounded to tf32 (K also column-pair-packed) for the attn kernel.
// ---------------------------------------------------------------------------
#define XST 132
#define WST 72
__global__ void __launch_bounds__(256, 1) proj_kernel(
    const float* __restrict__ x, const float* __restrict__ W,
    const float* __restrict__ bias, const int* __restrict__ npadd_p) {
  extern __shared__ float sm[];
  float* xh = sm;                        // [128][XST]
  float* xl = sm + 128 * XST;            // [128][XST]
  float* ws = sm + 2 * 128 * XST;        // [128][WST] (k-major, n cols 0..63)

  const int tid = threadIdx.x;
  const int lane = tid & 31;
  const int w = tid >> 5;
  const int tq = lane >> 2;
  const int tr = lane & 3;
  const int row0 = blockIdx.x * 128;
  const int col0 = blockIdx.y * 64;

  // stage x (hi/lo split, tf32-rounded)
#pragma unroll
  for (int it = 0; it < 16; ++it) {
    int idx = tid + it * 256;
    int r = idx >> 5, c4 = idx & 31;
    float4 v = *(const float4*)&x[(row0 + r) * CINP + c4 * 4];
    float4 h, l;
    h.x = tf32f(v.x); h.y = tf32f(v.y); h.z = tf32f(v.z); h.w = tf32f(v.w);
    l.x = tf32f(v.x - h.x); l.y = tf32f(v.y - h.y);
    l.z = tf32f(v.z - h.z); l.w = tf32f(v.w - h.w);
    *(float4*)&xh[r * XST + c4 * 4] = h;
    *(float4*)&xl[r * XST + c4 * 4] = l;
  }
  // stage W tile: natural [k][n] layout, tf32-rounded
#pragma unroll
  for (int it = 0; it < 8; ++it) {
    int idx = tid + it * 256;
    int k = idx >> 4, n4 = idx & 15;
    float4 v = *(const float4*)&W[k * (3 * NF) + col0 + n4 * 4];
    v.x = tf32f(v.x); v.y = tf32f(v.y); v.z = tf32f(v.z); v.w = tf32f(v.w);
    *(float4*)&ws[k * WST + n4 * 4] = v;
  }
  __syncthreads();

  float s[8][4];
#pragma unroll
  for (int n = 0; n < 8; ++n)
#pragma unroll
    for (int i = 0; i < 4; ++i) s[n][i] = 0.0f;

  const float* x0h = &xh[(16 * w + tq) * XST];
  const float* x1h = &xh[(16 * w + tq + 8) * XST];
  const float* x0l = &xl[(16 * w + tq) * XST];
  const float* x1l = &xl[(16 * w + tq + 8) * XST];

#pragma unroll
  for (int kk = 0; kk < 16; ++kk) {
    uint32_t ah[4], al[4];
    ah[0] = __float_as_uint(x0h[kk * 8 + tr]);
    ah[1] = __float_as_uint(x1h[kk * 8 + tr]);
    ah[2] = __float_as_uint(x0h[kk * 8 + tr + 4]);
    ah[3] = __float_as_uint(x1h[kk * 8 + tr + 4]);
    al[0] = __float_as_uint(x0l[kk * 8 + tr]);
    al[1] = __float_as_uint(x1l[kk * 8 + tr]);
    al[2] = __float_as_uint(x0l[kk * 8 + tr + 4]);
    al[3] = __float_as_uint(x1l[kk * 8 + tr + 4]);
#pragma unroll
    for (int nt = 0; nt < 8; ++nt) {
      uint32_t bb[2];
      const float* wp = &ws[(kk * 8 + tr) * WST + nt * 8 + tq];
      bb[0] = __float_as_uint(wp[0]);
      bb[1] = __float_as_uint(wp[4 * WST]);
      mma_tf32(s[nt], ah, bb);
      mma_tf32(s[nt], al, bb);
    }
  }

  // epilogue: bias, per-section routing (q: scale; k: pack; v: zero-pad)
  const int sec = blockIdx.y >> 1;
  const int wcb = (blockIdx.y & 1) * 64;
  const int npadd = *npadd_p;
  const int r0 = row0 + 16 * w + tq;
  const int r1 = r0 + 8;
#pragma unroll
  for (int nt = 0; nt < 8; ++nt) {
    int c0 = nt * 8 + 2 * tr;
    float b0 = bias[col0 + c0];
    float b1 = bias[col0 + c0 + 1];
    float v00 = s[nt][0] + b0, v01 = s[nt][1] + b1;
    float v10 = s[nt][2] + b0, v11 = s[nt][3] + b1;
    int wc0 = wcb + c0, wc1 = wc0 + 1;
    if (sec == 0) {
      g_Q[r0 * NF + wc0] = tf32f(v00 * QSCALE);
      g_Q[r0 * NF + wc1] = tf32f(v01 * QSCALE);
      g_Q[r1 * NF + wc0] = tf32f(v10 * QSCALE);
      g_Q[r1 * NF + wc1] = tf32f(v11 * QSCALE);
    } else if (sec == 1) {
      g_K[r0 * NF + packc(wc0)] = tf32f(v00);
      g_K[r0 * NF + packc(wc1)] = tf32f(v01);
      g_K[r1 * NF + packc(wc0)] = tf32f(v10);
      g_K[r1 * NF + packc(wc1)] = tf32f(v11);
    } else {
      g_V[r0 * NF + wc0] = (r0 >= npadd) ? tf32f(v00) : 0.0f;
      g_V[r0 * NF + wc1] = (r0 >= npadd) ? tf32f(v01) : 0.0f;
      g_V[r1 * NF + wc0] = (r1 >= npadd) ? tf32f(v10) : 0.0f;
      g_V[r1 * NF + wc1] = (r1 >= npadd) ? tf32f(v11) : 0.0f;
    }
  }
}

// ---------------------------------------------------------------------------
// Kernel 2: flash attention via mma.sync tf32, cp.async double-buffered K/V.
// CTA = (q tile of 128 rows, chunk of <=16 key tiles of 64).
// 8 warps; warp w owns rows 16w..16w+15 (warp-local softmax).
// Smem floats: Ks0 Vs0 Ks1 Vs1 (8704 each), Ps 8704.  Q staged in Ks1/Vs1.
// ---------------------------------------------------------------------------
#define KV_TILE 8704   // 64*136
__global__ void __launch_bounds__(256, 1) attn_kernel(const int* __restrict__ npadd_p) {
  extern __shared__ float sm[];
  float* Ps = sm + 4 * KV_TILE;
  float* Qs = sm + 2 * KV_TILE;          // staging: overlaps buf1 (freed after extract)

  const int tid = threadIdx.x;
  const int lane = tid & 31;
  const int w = tid >> 5;
  const int tq = lane >> 2;
  const int tr = lane & 3;

  const int qt = 63 - blockIdx.x;
  const int ch = blockIdx.y;
  const int kcount = 2 * (qt + 1);
  const int nch = (kcount + NKT - 1) / NKT;
  if (ch >= nch) return;
  const int k0 = ch * NKT;
  const int k1 = (k0 + NKT < kcount) ? (k0 + NKT) : kcount;
  const int npadd = *npadd_p;
  const int qrow0 = qt * BM;

  const uint32_t smem_base = smem_u32(sm);

  // ---- prologue: async-fetch tile k0 into buf0; stage Q into buf1 region ----
  {
    const int kbase = k0 * BN;
    uint32_t kb = smem_base;
    uint32_t vb = smem_base + KV_TILE * 4;
#pragma unroll
    for (int it = 0; it < 8; ++it) {
      int idx = tid + it * 256;
      int r = idx >> 5, c4 = idx & 31;
      cp16(kb + (r * KST + c4 * 4) * 4, &g_K[(kbase + r) * NF + c4 * 4]);
      cp16(vb + (r * VST + c4 * 4) * 4, &g_V[(kbase + r) * NF + c4 * 4]);
    }
    asm volatile("cp.async.commit_group;" ::: "memory");
  }
#pragma unroll
  for (int it = 0; it < 16; ++it) {
    int idx = tid + it * 256;
    int r = idx >> 5, c4 = idx & 31;
    *(float4*)&Qs[r * QST + c4 * 4] =
        *(const float4*)&g_Q[(qrow0 + r) * NF + c4 * 4];
  }
  __syncthreads();

  uint32_t qa[16][4];
  {
    const float* q0 = &Qs[(16 * w + tq) * QST];
    const float* q1 = &Qs[(16 * w + tq + 8) * QST];
#pragma unroll
    for (int kk = 0; kk < 16; ++kk) {
      qa[kk][0] = __float_as_uint(q0[kk * 8 + tr]);
      qa[kk][1] = __float_as_uint(q1[kk * 8 + tr]);
      qa[kk][2] = __float_as_uint(q0[kk * 8 + tr + 4]);
      qa[kk][3] = __float_as_uint(q1[kk * 8 + tr + 4]);
    }
  }

  const int r0g = qrow0 + 16 * w + tq;
  const int r1g = r0g + 8;
  float m0 = neg_inf(), m1 = neg_inf(), l0 = 0.0f, l1 = 0.0f;
  float o[16][4];
#pragma unroll
  for (int n = 0; n < 16; ++n)
#pragma unroll
    for (int i = 0; i < 4; ++i) o[n][i] = 0.0f;

  float* pw = Ps + w * 16 * PST;

  for (int kt = k0; kt < k1; ++kt) {
    const int buf = (kt - k0) & 1;
    const int kbase = kt * BN;
    __syncthreads();   // all warps done reading buf^1 (prev tile) & extraction

    // prefetch next tile into the other buffer
    if (kt + 1 < k1) {
      const int nb = (kt + 1) * BN;
      uint32_t kb = smem_base + (buf ^ 1) * 0 + ((buf ^ 1) ? 2 : 0) * KV_TILE * 4;
      uint32_t vb = kb + KV_TILE * 4;
#pragma unroll
      for (int it = 0; it < 8; ++it) {
        int idx = tid + it * 256;
        int r = idx >> 5, c4 = idx & 31;
        cp16(kb + (r * KST + c4 * 4) * 4, &g_K[(nb + r) * NF + c4 * 4]);
        cp16(vb + (r * VST + c4 * 4) * 4, &g_V[(nb + r) * NF + c4 * 4]);
      }
    }
    asm volatile("cp.async.commit_group;" ::: "memory");
    asm volatile("cp.async.wait_group 1;" ::: "memory");
    __syncthreads();   // current buf visible to all

    const float* Ks = sm + (buf ? 2 : 0) * KV_TILE;
    const float* Vs = Ks + KV_TILE;

    // ---- S = Q @ K^T (packed K: one float2 per B-frag) ----
    float s[8][4];
#pragma unroll
    for (int n = 0; n < 8; ++n)
#pragma unroll
      for (int i = 0; i < 4; ++i) s[n][i] = 0.0f;

#pragma unroll
    for (int kk = 0; kk < 16; ++kk) {
#pragma unroll
      for (int nt = 0; nt < 8; ++nt) {
        float2 kp = *(const float2*)&Ks[(nt * 8 + tq) * KST + kk * 8 + 2 * tr];
        uint32_t bb[2];
        bb[0] = __float_as_uint(kp.x);
        bb[1] = __float_as_uint(kp.y);
        mma_tf32(s[nt], qa[kk], bb);
      }
    }

    // ---- mask ----
    const bool needmask = (kbase + BN > qrow0) || (kbase < npadd) || (qrow0 < npadd);
    if (needmask) {
#pragma unroll
      for (int nt = 0; nt < 8; ++nt) {
        int j0 = kbase + nt * 8 + 2 * tr;
        int j1 = j0 + 1;
        if (j0 > r0g || j0 < npadd || r0g < npadd) s[nt][0] = neg_inf();
        if (j1 > r0g || j1 < npadd || r0g < npadd) s[nt][1] = neg_inf();
        if (j0 > r1g || j0 < npadd || r1g < npadd) s[nt][2] = neg_inf();
        if (j1 > r1g || j1 < npadd || r1g < npadd) s[nt][3] = neg_inf();
      }
    }

    // ---- warp-local online softmax ----
    float mx0 = neg_inf(), mx1 = neg_inf();
#pragma unroll
    for (int nt = 0; nt < 8; ++nt) {
      mx0 = fmaxf(mx0, fmaxf(s[nt][0], s[nt][1]));
      mx1 = fmaxf(mx1, fmaxf(s[nt][2], s[nt][3]));
    }
    mx0 = fmaxf(mx0, __shfl_xor_sync(0xffffffffu, mx0, 1));
    mx0 = fmaxf(mx0, __shfl_xor_sync(0xffffffffu, mx0, 2));
    mx1 = fmaxf(mx1, __shfl_xor_sync(0xffffffffu, mx1, 1));
    mx1 = fmaxf(mx1, __shfl_xor_sync(0xffffffffu, mx1, 2));

    float mn0 = fmaxf(m0, mx0);
    float mn1 = fmaxf(m1, mx1);
    float a0 = (mn0 == neg_inf()) ? 1.0f : __expf(m0 - mn0);
    float a1 = (mn1 == neg_inf()) ? 1.0f : __expf(m1 - mn1);
    m0 = mn0; m1 = mn1;
    const bool dead0 = (mn0 == neg_inf());
    const bool dead1 = (mn1 == neg_inf());

#pragma unroll
    for (int n = 0; n < 16; ++n) {
      o[n][0] *= a0; o[n][1] *= a0;
      o[n][2] *= a1; o[n][3] *= a1;
    }

    float sum0 = 0.0f, sum1 = 0.0f;
#pragma unroll
    for (int nt = 0; nt < 8; ++nt) {
      float p0 = dead0 ? 0.0f : __expf(s[nt][0] - mn0);
      float p1 = dead0 ? 0.0f : __expf(s[nt][1] - mn0);
      float p2 = dead1 ? 0.0f : __expf(s[nt][2] - mn1);
      float p3 = dead1 ? 0.0f : __expf(s[nt][3] - mn1);
      sum0 += p0 + p1; sum1 += p2 + p3;
      s[nt][0] = p0; s[nt][1] = p1; s[nt][2] = p2; s[nt][3] = p3;
    }
    sum0 += __shfl_xor_sync(0xffffffffu, sum0, 1);
    sum0 += __shfl_xor_sync(0xffffffffu, sum0, 2);
    sum1 += __shfl_xor_sync(0xffffffffu, sum1, 1);
    sum1 += __shfl_xor_sync(0xffffffffu, sum1, 2);
    l0 = l0 * a0 + sum0;
    l1 = l1 * a1 + sum1;

    // ---- P: C-fragment -> smem -> A-fragment ----
#pragma unroll
    for (int nt = 0; nt < 8; ++nt) {
      *(float2*)&pw[tq * PST + nt * 8 + 2 * tr] =
          make_float2(tf32f(s[nt][0]), tf32f(s[nt][1]));
      *(float2*)&pw[(tq + 8) * PST + nt * 8 + 2 * tr] =
          make_float2(tf32f(s[nt][2]), tf32f(s[nt][3]));
    }
    __syncwarp();

    // ---- O += P @ V ----
#pragma unroll
    for (int kt8 = 0; kt8 < 8; ++kt8) {
      uint32_t pa[4];
      pa[0] = __float_as_uint(pw[tq * PST + kt8 * 8 + tr]);
      pa[1] = __float_as_uint(pw[(tq + 8) * PST + kt8 * 8 + tr]);
      pa[2] = __float_as_uint(pw[tq * PST + kt8 * 8 + tr + 4]);
      pa[3] = __float_as_uint(pw[(tq + 8) * PST + kt8 * 8 + tr + 4]);
#pragma unroll
      for (int nt2 = 0; nt2 < 16; ++nt2) {
        uint32_t bb[2];
        const float* vp = &Vs[(kt8 * 8 + tr) * VST + nt2 * 8 + tq];
        bb[0] = __float_as_uint(vp[0]);
        bb[1] = __float_as_uint(vp[4 * VST]);
        mma_tf32(o[nt2], pa, bb);
      }
    }
    __syncwarp();
  }

  // ---- write split partials (unnormalized) ----
  float* ob0 = &g_O[((size_t)ch * T + r0g) * NF];
  float* ob1 = &g_O[((size_t)ch * T + r1g) * NF];
#pragma unroll
  for (int nt2 = 0; nt2 < 16; ++nt2) {
    int c = nt2 * 8 + 2 * tr;
    *(float2*)&ob0[c] = make_float2(o[nt2][0], o[nt2][1]);
    *(float2*)&ob1[c] = make_float2(o[nt2][2], o[nt2][3]);
  }
  if (tr == 0) {
    g_M[ch * T + r0g] = m0; g_M[ch * T + r1g] = m1;
    g_L[ch * T + r0g] = l0; g_L[ch * T + r1g] = l1;
  }
}

// ---------------------------------------------------------------------------
// Kernel 3: combine split partials.
// ---------------------------------------------------------------------------
__global__ void __launch_bounds__(256) combine_kernel(float* __restrict__ out) {
  const int tid = threadIdx.x;
  const int t = blockIdx.x * 2 + (tid >> 7);
  const int c = tid & 127;
  const int qt = t >> 7;
  const int nch = (qt + 8) / 8;

  float m[NSPLIT_MAX], l[NSPLIT_MAX];
  float mx = neg_inf();
  for (int s = 0; s < nch; ++s) {
    m[s] = g_M[s * T + t];
    l[s] = g_L[s * T + t];
    mx = fmaxf(mx, m[s]);
  }
  if (mx == neg_inf()) { out[t * NF + c] = 0.0f; return; }
  float den = 0.0f, num = 0.0f;
  for (int s = 0; s < nch; ++s) {
    float wgt = (m[s] == neg_inf()) ? 0.0f : __expf(m[s] - mx);
    den += wgt * l[s];
    num = fmaf(wgt, g_O[((size_t)s * T + t) * NF + c], num);
  }
  out[t * NF + c] = num / den;
}

// ---------------------------------------------------------------------------
extern "C" void kernel_launch(void* const* d_in, const int* in_sizes, int n_in,
                              void* d_out, int out_size) {
  const float* x = (const float*)d_in[0];
  const float* W = (const float*)d_in[1];
  const float* b = (const float*)d_in[2];
  const int* npadd = (const int*)d_in[3];
  float* out = (float*)d_out;

  constexpr int PROJ_SMEM = (2 * 128 * XST + 128 * WST) * (int)sizeof(float); // ~168KB
  constexpr int ATTN_SMEM = (5 * KV_TILE) * (int)sizeof(float);               // ~170KB
  cudaFuncSetAttribute(proj_kernel, cudaFuncAttributeMaxDynamicSharedMemorySize, PROJ_SMEM);
  cudaFuncSetAttribute(attn_kernel, cudaFuncAttributeMaxDynamicSharedMemorySize, ATTN_SMEM);

  proj_kernel<<<dim3(64, 6), 256, PROJ_SMEM>>>(x, W, b, npadd);
  attn_kernel<<<dim3(64, NSPLIT_MAX), 256, ATTN_SMEM>>>(npadd);
  combine_kernel<<<T / 2, 256>>>(out);
}

// round 5
// speedup vs baseline: 4.6891x; 1.5385x over previous
#include <cuda_runtime.h>
#include <cuda_fp16.h>
#include <cuda_bf16.h>
#include <cstdint>

// Problem constants
#define T      8192
#define NF     128
#define CINP   128
#define QSCALE 0.08838834764831845f  // 1/sqrt(128)
#define NSPLIT_MAX 8

// Attention tiling
#define BM 128          // query rows per CTA
#define BN 64           // keys per inner tile
#define NKT 16          // key tiles (of 64) per chunk -> 1024 keys/chunk
#define KSTB 288        // K smem row stride BYTES (128 bf16 packed + pad)
#define VSTB 160        // Vt smem row stride BYTES (64 fp16 packed + pad)
#define PSTB 160        // P smem row stride BYTES (64 fp16 packed + pad)
#define QSTB 288        // Q smem row stride BYTES

// smem layout (bytes)
#define K_TILE  (64 * KSTB)        // 18432
#define V_TILE  (128 * VSTB)       // 20480
#define KV_BUF  (K_TILE + V_TILE)  // 38912
#define PS_OFF  (2 * KV_BUF)       // 77824
#define PS_SIZE (8 * 16 * PSTB)    // 20480
#define QS_OFF  (PS_OFF + PS_SIZE) // 98304
#define QS_SIZE (128 * QSTB)       // 36864
#define ATTN_SMEM (QS_OFF + QS_SIZE)  // 135168

// Scratch (no cudaMalloc allowed).  Packed fragment-order operand tensors.
__device__ __nv_bfloat16 g_Qh[T * NF];   // [row][packc16(d)]
__device__ __nv_bfloat16 g_Kh[T * NF];   // [key][packc16(d)]
__device__ __half        g_Vh[NF * T];   // [d][packc16(key)] (transposed)
__device__ float g_O[NSPLIT_MAX * T * NF];
__device__ float g_M[NSPLIT_MAX * T];
__device__ float g_L[NSPLIT_MAX * T];

__device__ __forceinline__ float neg_inf() { return __int_as_float(0xff800000u); }

__device__ __forceinline__ uint32_t f2tf32(float f) {
  uint32_t u;
  asm("cvt.rna.tf32.f32 %0, %1;" : "=r"(u) : "f"(f));
  return u;
}
__device__ __forceinline__ float tf32f(float f) {
  return __uint_as_float(f2tf32(f));
}

// fragment-order permutation within each 16-group: [0,1,8,9,2,3,10,11,4,5,12,13,6,7,14,15]
// maps original index c to packed position (keeps 16-group base).
__device__ __forceinline__ int packc16(int c) {
  int u = c & 7, pr = (c >> 3) & 1;
  return (c & ~15) | (((u >> 1) << 2) | (u & 1) | (pr << 1));
}

// D += A(16x8) * B(8x8), tf32, f32 accum (projection)
__device__ __forceinline__ void mma_tf32(float* d, const uint32_t* a,
                                         const uint32_t* b) {
  asm volatile(
      "mma.sync.aligned.m16n8k8.row.col.f32.tf32.tf32.f32 "
      "{%0,%1,%2,%3}, {%4,%5,%6,%7}, {%8,%9}, {%0,%1,%2,%3};\n"
      : "+f"(d[0]), "+f"(d[1]), "+f"(d[2]), "+f"(d[3])
      : "r"(a[0]), "r"(a[1]), "r"(a[2]), "r"(a[3]), "r"(b[0]), "r"(b[1]));
}
// D += A(16x16) * B(16x8), bf16, f32 accum (QK)
__device__ __forceinline__ void mma_bf16(float* d, const uint32_t* a,
                                         const uint32_t* b) {
  asm volatile(
      "mma.sync.aligned.m16n8k16.row.col.f32.bf16.bf16.f32 "
      "{%0,%1,%2,%3}, {%4,%5,%6,%7}, {%8,%9}, {%0,%1,%2,%3};\n"
      : "+f"(d[0]), "+f"(d[1]), "+f"(d[2]), "+f"(d[3])
      : "r"(a[0]), "r"(a[1]), "r"(a[2]), "r"(a[3]), "r"(b[0]), "r"(b[1]));
}
// D += A(16x16) * B(16x8), fp16, f32 accum (PV)
__device__ __forceinline__ void mma_f16(float* d, const uint32_t* a,
                                        const uint32_t* b) {
  asm volatile(
      "mma.sync.aligned.m16n8k16.row.col.f32.f16.f16.f32 "
      "{%0,%1,%2,%3}, {%4,%5,%6,%7}, {%8,%9}, {%0,%1,%2,%3};\n"
      : "+f"(d[0]), "+f"(d[1]), "+f"(d[2]), "+f"(d[3])
      : "r"(a[0]), "r"(a[1]), "r"(a[2]), "r"(a[3]), "r"(b[0]), "r"(b[1]));
}

__device__ __forceinline__ uint32_t smem_u32(const void* p) {
  uint32_t a;
  asm("{ .reg .u64 t; cvta.to.shared.u64 t, %1; cvt.u32.u64 %0, t; }"
      : "=r"(a) : "l"(p));
  return a;
}
__device__ __forceinline__ void cp16(uint32_t daddr, const void* src) {
  asm volatile("cp.async.cg.shared.global [%0], [%1], 16;"
               :: "r"(daddr), "l"(src));
}

// ---------------------------------------------------------------------------
// Kernel 1: QKV projection via mma.sync tf32, 2-term split (lo computed in
// registers from staged fp32 x).  CTA = (128 rows, 64 cols); grid (64, 6).
// Epilogue writes bf16/fp16 fragment-packed operand tensors.
// ---------------------------------------------------------------------------
#define XST 132
#define WST 72
__global__ void __launch_bounds__(256, 2) proj_kernel(
    const float* __restrict__ x, const float* __restrict__ W,
    const float* __restrict__ bias, const int* __restrict__ npadd_p) {
  extern __shared__ float sm[];
  float* xs = sm;                 // [128][XST] fp32
  float* ws = sm + 128 * XST;     // [128][WST] tf32-rounded

  const int tid = threadIdx.x;
  const int lane = tid & 31;
  const int w = tid >> 5;
  const int tq = lane >> 2;
  const int tr = lane & 3;
  const int row0 = blockIdx.x * 128;
  const int col0 = blockIdx.y * 64;

#pragma unroll
  for (int it = 0; it < 16; ++it) {
    int idx = tid + it * 256;
    int r = idx >> 5, c4 = idx & 31;
    *(float4*)&xs[r * XST + c4 * 4] =
        *(const float4*)&x[(row0 + r) * CINP + c4 * 4];
  }
#pragma unroll
  for (int it = 0; it < 8; ++it) {
    int idx = tid + it * 256;
    int k = idx >> 4, n4 = idx & 15;
    float4 v = *(const float4*)&W[k * (3 * NF) + col0 + n4 * 4];
    v.x = tf32f(v.x); v.y = tf32f(v.y); v.z = tf32f(v.z); v.w = tf32f(v.w);
    *(float4*)&ws[k * WST + n4 * 4] = v;
  }
  __syncthreads();

  float s[8][4];
#pragma unroll
  for (int n = 0; n < 8; ++n)
#pragma unroll
    for (int i = 0; i < 4; ++i) s[n][i] = 0.0f;

  const float* x0 = &xs[(16 * w + tq) * XST];
  const float* x1 = &xs[(16 * w + tq + 8) * XST];

#pragma unroll
  for (int kk = 0; kk < 16; ++kk) {
    float f0 = x0[kk * 8 + tr];
    float f1 = x1[kk * 8 + tr];
    float f2 = x0[kk * 8 + tr + 4];
    float f3 = x1[kk * 8 + tr + 4];
    uint32_t ah[4], al[4];
    ah[0] = f2tf32(f0); ah[1] = f2tf32(f1);
    ah[2] = f2tf32(f2); ah[3] = f2tf32(f3);
    al[0] = f2tf32(f0 - __uint_as_float(ah[0]));
    al[1] = f2tf32(f1 - __uint_as_float(ah[1]));
    al[2] = f2tf32(f2 - __uint_as_float(ah[2]));
    al[3] = f2tf32(f3 - __uint_as_float(ah[3]));
#pragma unroll
    for (int nt = 0; nt < 8; ++nt) {
      uint32_t bb[2];
      const float* wp = &ws[(kk * 8 + tr) * WST + nt * 8 + tq];
      bb[0] = __float_as_uint(wp[0]);
      bb[1] = __float_as_uint(wp[4 * WST]);
      mma_tf32(s[nt], ah, bb);
      mma_tf32(s[nt], al, bb);
    }
  }

  const int sec = blockIdx.y >> 1;          // 0:q 1:k 2:v
  const int wcb = (blockIdx.y & 1) * 64;
  const int npadd = *npadd_p;
  const int r0 = row0 + 16 * w + tq;
  const int r1 = r0 + 8;
#pragma unroll
  for (int nt = 0; nt < 8; ++nt) {
    int c0 = nt * 8 + 2 * tr;
    float b0 = bias[col0 + c0];
    float b1 = bias[col0 + c0 + 1];
    float v00 = s[nt][0] + b0, v01 = s[nt][1] + b1;
    float v10 = s[nt][2] + b0, v11 = s[nt][3] + b1;
    int wc0 = wcb + c0, wc1 = wc0 + 1;
    if (sec == 0) {
      g_Qh[r0 * NF + packc16(wc0)] = __float2bfloat16_rn(v00 * QSCALE);
      g_Qh[r0 * NF + packc16(wc1)] = __float2bfloat16_rn(v01 * QSCALE);
      g_Qh[r1 * NF + packc16(wc0)] = __float2bfloat16_rn(v10 * QSCALE);
      g_Qh[r1 * NF + packc16(wc1)] = __float2bfloat16_rn(v11 * QSCALE);
    } else if (sec == 1) {
      g_Kh[r0 * NF + packc16(wc0)] = __float2bfloat16_rn(v00);
      g_Kh[r0 * NF + packc16(wc1)] = __float2bfloat16_rn(v01);
      g_Kh[r1 * NF + packc16(wc0)] = __float2bfloat16_rn(v10);
      g_Kh[r1 * NF + packc16(wc1)] = __float2bfloat16_rn(v11);
    } else {
      int pk0 = packc16(r0), pk1 = packc16(r1);
      g_Vh[wc0 * T + pk0] = __float2half_rn((r0 >= npadd) ? v00 : 0.0f);
      g_Vh[wc1 * T + pk0] = __float2half_rn((r0 >= npadd) ? v01 : 0.0f);
      g_Vh[wc0 * T + pk1] = __float2half_rn((r1 >= npadd) ? v10 : 0.0f);
      g_Vh[wc1 * T + pk1] = __float2half_rn((r1 >= npadd) ? v11 : 0.0f);
    }
  }
}

// ---------------------------------------------------------------------------
// Kernel 2: flash attention, bf16 QK + fp16 PV (k16 mma), cp.async
// double-buffered K/V.  8 warps; warp w owns rows 16w..16w+15.
// ---------------------------------------------------------------------------
__global__ void __launch_bounds__(256, 1) attn_kernel(const int* __restrict__ npadd_p) {
  extern __shared__ char smc[];

  const int tid = threadIdx.x;
  const int lane = tid & 31;
  const int w = tid >> 5;
  const int tq = lane >> 2;
  const int tr = lane & 3;

  const int qt = 63 - blockIdx.x;
  const int ch = blockIdx.y;
  const int kcount = 2 * (qt + 1);
  const int nch = (kcount + NKT - 1) / NKT;
  if (ch >= nch) return;
  const int k0 = ch * NKT;
  const int k1 = (k0 + NKT < kcount) ? (k0 + NKT) : kcount;
  const int npadd = *npadd_p;
  const int qrow0 = qt * BM;

  const uint32_t sb = smem_u32(smc);

  // ---- prologue: async-fetch K/V tile k0 into buf0 + Q tile ----
  {
    const int kbase = k0 * BN;
    const char* ksrc = (const char*)g_Kh + (size_t)kbase * (NF * 2);
#pragma unroll
    for (int it = 0; it < 4; ++it) {
      int idx = tid + it * 256;
      int r = idx >> 4, seg = idx & 15;
      cp16(sb + r * KSTB + seg * 16, ksrc + r * (NF * 2) + seg * 16);
    }
    const char* vsrc = (const char*)g_Vh + (size_t)kbase * 2;
#pragma unroll
    for (int it = 0; it < 4; ++it) {
      int idx = tid + it * 256;
      int r = idx >> 3, seg = idx & 7;
      cp16(sb + K_TILE + r * VSTB + seg * 16, vsrc + (size_t)r * (T * 2) + seg * 16);
    }
    const char* qsrc = (const char*)g_Qh + (size_t)qrow0 * (NF * 2);
#pragma unroll
    for (int it = 0; it < 8; ++it) {
      int idx = tid + it * 256;
      int r = idx >> 4, seg = idx & 15;
      cp16(sb + QS_OFF + r * QSTB + seg * 16, qsrc + r * (NF * 2) + seg * 16);
    }
    asm volatile("cp.async.commit_group;" ::: "memory");
    asm volatile("cp.async.wait_group 0;" ::: "memory");
  }
  __syncthreads();

  // ---- extract Q A-fragments (bf16, packed: one LDS.64 per row per kk) ----
  uint32_t qa[8][4];
  {
    const char* q0 = smc + QS_OFF + (16 * w + tq) * QSTB + tr * 8;
    const char* q1 = q0 + 8 * QSTB;
#pragma unroll
    for (int kk = 0; kk < 8; ++kk) {
      uint2 l0 = *(const uint2*)(q0 + kk * 32);
      uint2 l1 = *(const uint2*)(q1 + kk * 32);
      qa[kk][0] = l0.x; qa[kk][1] = l1.x; qa[kk][2] = l0.y; qa[kk][3] = l1.y;
    }
  }

  const int r0g = qrow0 + 16 * w + tq;
  const int r1g = r0g + 8;
  float m0 = neg_inf(), m1 = neg_inf(), l0s = 0.0f, l1s = 0.0f;
  float o[16][4];
#pragma unroll
  for (int n = 0; n < 16; ++n)
#pragma unroll
    for (int i = 0; i < 4; ++i) o[n][i] = 0.0f;

  char* pw = smc + PS_OFF + w * 16 * PSTB;

  for (int kt = k0; kt < k1; ++kt) {
    const int buf = (kt - k0) & 1;
    const int kbase = kt * BN;
    __syncthreads();   // all warps done reading buf^1

    if (kt + 1 < k1) {
      const int nb = (kt + 1) * BN;
      const uint32_t kb = sb + (buf ^ 1) * KV_BUF;
      const char* ksrc = (const char*)g_Kh + (size_t)nb * (NF * 2);
#pragma unroll
      for (int it = 0; it < 4; ++it) {
        int idx = tid + it * 256;
        int r = idx >> 4, seg = idx & 15;
        cp16(kb + r * KSTB + seg * 16, ksrc + r * (NF * 2) + seg * 16);
      }
      const char* vsrc = (const char*)g_Vh + (size_t)nb * 2;
#pragma unroll
      for (int it = 0; it < 4; ++it) {
        int idx = tid + it * 256;
        int r = idx >> 3, seg = idx & 7;
        cp16(kb + K_TILE + r * VSTB + seg * 16, vsrc + (size_t)r * (T * 2) + seg * 16);
      }
    }
    asm volatile("cp.async.commit_group;" ::: "memory");
    asm volatile("cp.async.wait_group 1;" ::: "memory");
    __syncthreads();

    const char* Ks = smc + buf * KV_BUF;
    const char* Vs = Ks + K_TILE;

    // ---- S = Q @ K^T : 8 kk(16) x 8 nt, one LDS.64 per B-frag ----
    float s[8][4];
#pragma unroll
    for (int n = 0; n < 8; ++n)
#pragma unroll
      for (int i = 0; i < 4; ++i) s[n][i] = 0.0f;

#pragma unroll
    for (int kk = 0; kk < 8; ++kk) {
#pragma unroll
      for (int nt = 0; nt < 8; ++nt) {
        uint2 bb = *(const uint2*)(Ks + (nt * 8 + tq) * KSTB + kk * 32 + tr * 8);
        mma_bf16(s[nt], qa[kk], (const uint32_t*)&bb);
      }
    }

    // ---- mask ----
    const bool needmask = (kbase + BN > qrow0) || (kbase < npadd) || (qrow0 < npadd);
    if (needmask) {
#pragma unroll
      for (int nt = 0; nt < 8; ++nt) {
        int j0 = kbase + nt * 8 + 2 * tr;
        int j1 = j0 + 1;
        if (j0 > r0g || j0 < npadd || r0g < npadd) s[nt][0] = neg_inf();
        if (j1 > r0g || j1 < npadd || r0g < npadd) s[nt][1] = neg_inf();
        if (j0 > r1g || j0 < npadd || r1g < npadd) s[nt][2] = neg_inf();
        if (j1 > r1g || j1 < npadd || r1g < npadd) s[nt][3] = neg_inf();
      }
    }

    // ---- warp-local online softmax ----
    float mx0 = neg_inf(), mx1 = neg_inf();
#pragma unroll
    for (int nt = 0; nt < 8; ++nt) {
      mx0 = fmaxf(mx0, fmaxf(s[nt][0], s[nt][1]));
      mx1 = fmaxf(mx1, fmaxf(s[nt][2], s[nt][3]));
    }
    mx0 = fmaxf(mx0, __shfl_xor_sync(0xffffffffu, mx0, 1));
    mx0 = fmaxf(mx0, __shfl_xor_sync(0xffffffffu, mx0, 2));
    mx1 = fmaxf(mx1, __shfl_xor_sync(0xffffffffu, mx1, 1));
    mx1 = fmaxf(mx1, __shfl_xor_sync(0xffffffffu, mx1, 2));

    float mn0 = fmaxf(m0, mx0);
    float mn1 = fmaxf(m1, mx1);
    float a0 = (mn0 == neg_inf()) ? 1.0f : __expf(m0 - mn0);
    float a1 = (mn1 == neg_inf()) ? 1.0f : __expf(m1 - mn1);
    m0 = mn0; m1 = mn1;
    const bool dead0 = (mn0 == neg_inf());
    const bool dead1 = (mn1 == neg_inf());

#pragma unroll
    for (int n = 0; n < 16; ++n) {
      o[n][0] *= a0; o[n][1] *= a0;
      o[n][2] *= a1; o[n][3] *= a1;
    }

    float sum0 = 0.0f, sum1 = 0.0f;
#pragma unroll
    for (int nt = 0; nt < 8; ++nt) {
      float p0 = dead0 ? 0.0f : __expf(s[nt][0] - mn0);
      float p1 = dead0 ? 0.0f : __expf(s[nt][1] - mn0);
      float p2 = dead1 ? 0.0f : __expf(s[nt][2] - mn1);
      float p3 = dead1 ? 0.0f : __expf(s[nt][3] - mn1);
      sum0 += p0 + p1; sum1 += p2 + p3;
      // store P as fp16, fragment-packed along keys
      int off = ((nt >> 1) << 5) + tr * 8 + ((nt & 1) << 2);
      *(__half2*)(pw + tq * PSTB + off) = __floats2half2_rn(p0, p1);
      *(__half2*)(pw + (tq + 8) * PSTB + off) = __floats2half2_rn(p2, p3);
    }
    sum0 += __shfl_xor_sync(0xffffffffu, sum0, 1);
    sum0 += __shfl_xor_sync(0xffffffffu, sum0, 2);
    sum1 += __shfl_xor_sync(0xffffffffu, sum1, 1);
    sum1 += __shfl_xor_sync(0xffffffffu, sum1, 2);
    l0s = l0s * a0 + sum0;
    l1s = l1s * a1 + sum1;
    __syncwarp();

    // ---- O += P @ V : 4 kt(16 keys) x 16 nt2(8 d) ----
#pragma unroll
    for (int ktk = 0; ktk < 4; ++ktk) {
      uint2 p0 = *(const uint2*)(pw + tq * PSTB + ktk * 32 + tr * 8);
      uint2 p1 = *(const uint2*)(pw + (tq + 8) * PSTB + ktk * 32 + tr * 8);
      uint32_t pa[4] = {p0.x, p1.x, p0.y, p1.y};
#pragma unroll
      for (int nt2 = 0; nt2 < 16; ++nt2) {
        uint2 bb = *(const uint2*)(Vs + (nt2 * 8 + tq) * VSTB + ktk * 32 + tr * 8);
        mma_f16(o[nt2], pa, (const uint32_t*)&bb);
      }
    }
    __syncwarp();
  }

  // ---- write split partials (unnormalized) ----
  float* ob0 = &g_O[((size_t)ch * T + r0g) * NF];
  float* ob1 = &g_O[((size_t)ch * T + r1g) * NF];
#pragma unroll
  for (int nt2 = 0; nt2 < 16; ++nt2) {
    int c = nt2 * 8 + 2 * tr;
    *(float2*)&ob0[c] = make_float2(o[nt2][0], o[nt2][1]);
    *(float2*)&ob1[c] = make_float2(o[nt2][2], o[nt2][3]);
  }
  if (tr == 0) {
    g_M[ch * T + r0g] = m0; g_M[ch * T + r1g] = m1;
    g_L[ch * T + r0g] = l0s; g_L[ch * T + r1g] = l1s;
  }
}

// ---------------------------------------------------------------------------
// Kernel 3: combine split partials.
// ---------------------------------------------------------------------------
__global__ void __launch_bounds__(256) combine_kernel(float* __restrict__ out) {
  const int tid = threadIdx.x;
  const int t = blockIdx.x * 2 + (tid >> 7);
  const int c = tid & 127;
  const int qt = t >> 7;
  const int nch = (qt + 8) / 8;

  float m[NSPLIT_MAX], l[NSPLIT_MAX];
  float mx = neg_inf();
  for (int s = 0; s < nch; ++s) {
    m[s] = g_M[s * T + t];
    l[s] = g_L[s * T + t];
    mx = fmaxf(mx, m[s]);
  }
  if (mx == neg_inf()) { out[t * NF + c] = 0.0f; return; }
  float den = 0.0f, num = 0.0f;
  for (int s = 0; s < nch; ++s) {
    float wgt = (m[s] == neg_inf()) ? 0.0f : __expf(m[s] - mx);
    den += wgt * l[s];
    num = fmaf(wgt, g_O[((size_t)s * T + t) * NF + c], num);
  }
  out[t * NF + c] = num / den;
}

// ---------------------------------------------------------------------------
extern "C" void kernel_launch(void* const* d_in, const int* in_sizes, int n_in,
                              void* d_out, int out_size) {
  const float* x = (const float*)d_in[0];
  const float* W = (const float*)d_in[1];
  const float* b = (const float*)d_in[2];
  const int* npadd = (const int*)d_in[3];
  float* out = (float*)d_out;

  constexpr int PROJ_SMEM = (128 * XST + 128 * WST) * (int)sizeof(float);  // ~102KB
  cudaFuncSetAttribute(proj_kernel, cudaFuncAttributeMaxDynamicSharedMemorySize, PROJ_SMEM);
  cudaFuncSetAttribute(attn_kernel, cudaFuncAttributeMaxDynamicSharedMemorySize, ATTN_SMEM);

  proj_kernel<<<dim3(64, 6), 256, PROJ_SMEM>>>(x, W, b, npadd);
  attn_kernel<<<dim3(64, NSPLIT_MAX), 256, ATTN_SMEM>>>(npadd);
  combine_kernel<<<T / 2, 256>>>(out);
}

// round 6
// speedup vs baseline: 5.2618x; 1.1222x over previous
#include <cuda_runtime.h>
#include <cuda_fp16.h>
#include <cuda_bf16.h>
#include <cstdint>

// Problem constants
#define T      8192
#define NF     128
#define CINP   128
#define LOG2E  1.4426950408889634f
#define QSCALE 0.08838834764831845f  // 1/sqrt(128)
#define NSPLIT_MAX 8

// Attention tiling
#define BM 128          // query rows per CTA
#define BN 64           // keys per inner tile
#define NKT 16          // key tiles (of 64) per chunk -> 1024 keys/chunk
#define KSTB 288        // K smem row stride BYTES
#define VSTB 160        // Vt smem row stride BYTES
#define PSTB 160        // P smem row stride BYTES
#define QSTB 288        // Q smem row stride BYTES

// smem layout (bytes) — single KV buffer, resident Q  => 2 CTAs/SM
#define K_TILE  (64 * KSTB)          // 18432
#define V_TILE  (128 * VSTB)         // 20480
#define KV_BUF  (K_TILE + V_TILE)    // 38912
#define PS_OFF  KV_BUF               // 38912
#define PS_SIZE (8 * 16 * PSTB)      // 20480
#define QS_OFF  (PS_OFF + PS_SIZE)   // 59392
#define QS_SIZE (128 * QSTB)         // 36864
#define ATTN_SMEM (QS_OFF + QS_SIZE) // 96256

// Scratch (no cudaMalloc allowed).  Packed fragment-order operand tensors.
__device__ __nv_bfloat16 g_Qh[T * NF];   // [row][packc16(d)], scaled by QSCALE*log2e
__device__ __nv_bfloat16 g_Kh[T * NF];   // [key][packc16(d)]
__device__ __half        g_Vh[NF * T];   // [d][packc16(key)] (transposed)
__device__ float g_O[NSPLIT_MAX * T * NF];
__device__ float g_M[NSPLIT_MAX * T];    // exp2-domain row max
__device__ float g_L[NSPLIT_MAX * T];

__device__ __forceinline__ float neg_inf() { return __int_as_float(0xff800000u); }

__device__ __forceinline__ uint32_t f2tf32(float f) {
  uint32_t u;
  asm("cvt.rna.tf32.f32 %0, %1;" : "=r"(u) : "f"(f));
  return u;
}
__device__ __forceinline__ float tf32f(float f) {
  return __uint_as_float(f2tf32(f));
}

// fragment-order permutation within each 16-group
__device__ __forceinline__ int packc16(int c) {
  int u = c & 7, pr = (c >> 3) & 1;
  return (c & ~15) | (((u >> 1) << 2) | (u & 1) | (pr << 1));
}

__device__ __forceinline__ void mma_tf32(float* d, const uint32_t* a,
                                         const uint32_t* b) {
  asm volatile(
      "mma.sync.aligned.m16n8k8.row.col.f32.tf32.tf32.f32 "
      "{%0,%1,%2,%3}, {%4,%5,%6,%7}, {%8,%9}, {%0,%1,%2,%3};\n"
      : "+f"(d[0]), "+f"(d[1]), "+f"(d[2]), "+f"(d[3])
      : "r"(a[0]), "r"(a[1]), "r"(a[2]), "r"(a[3]), "r"(b[0]), "r"(b[1]));
}
__device__ __forceinline__ void mma_bf16(float* d, const uint32_t* a,
                                         const uint32_t* b) {
  asm volatile(
      "mma.sync.aligned.m16n8k16.row.col.f32.bf16.bf16.f32 "
      "{%0,%1,%2,%3}, {%4,%5,%6,%7}, {%8,%9}, {%0,%1,%2,%3};\n"
      : "+f"(d[0]), "+f"(d[1]), "+f"(d[2]), "+f"(d[3])
      : "r"(a[0]), "r"(a[1]), "r"(a[2]), "r"(a[3]), "r"(b[0]), "r"(b[1]));
}
__device__ __forceinline__ void mma_f16(float* d, const uint32_t* a,
                                        const uint32_t* b) {
  asm volatile(
      "mma.sync.aligned.m16n8k16.row.col.f32.f16.f16.f32 "
      "{%0,%1,%2,%3}, {%4,%5,%6,%7}, {%8,%9}, {%0,%1,%2,%3};\n"
      : "+f"(d[0]), "+f"(d[1]), "+f"(d[2]), "+f"(d[3])
      : "r"(a[0]), "r"(a[1]), "r"(a[2]), "r"(a[3]), "r"(b[0]), "r"(b[1]));
}

__device__ __forceinline__ uint32_t smem_u32(const void* p) {
  uint32_t a;
  asm("{ .reg .u64 t; cvta.to.shared.u64 t, %1; cvt.u32.u64 %0, t; }"
      : "=r"(a) : "l"(p));
  return a;
}
__device__ __forceinline__ void cp16(uint32_t daddr, const void* src) {
  asm volatile("cp.async.cg.shared.global [%0], [%1], 16;"
               :: "r"(daddr), "l"(src));
}

// ---------------------------------------------------------------------------
// Kernel 1: QKV projection via mma.sync tf32, 2-term split.
// ---------------------------------------------------------------------------
#define XST 132
#define WST 72
__global__ void __launch_bounds__(256, 2) proj_kernel(
    const float* __restrict__ x, const float* __restrict__ W,
    const float* __restrict__ bias, const int* __restrict__ npadd_p) {
  extern __shared__ float sm[];
  float* xs = sm;                 // [128][XST] fp32
  float* ws = sm + 128 * XST;     // [128][WST] tf32-rounded

  const int tid = threadIdx.x;
  const int lane = tid & 31;
  const int w = tid >> 5;
  const int tq = lane >> 2;
  const int tr = lane & 3;
  const int row0 = blockIdx.x * 128;
  const int col0 = blockIdx.y * 64;

#pragma unroll
  for (int it = 0; it < 16; ++it) {
    int idx = tid + it * 256;
    int r = idx >> 5, c4 = idx & 31;
    *(float4*)&xs[r * XST + c4 * 4] =
        *(const float4*)&x[(row0 + r) * CINP + c4 * 4];
  }
#pragma unroll
  for (int it = 0; it < 8; ++it) {
    int idx = tid + it * 256;
    int k = idx >> 4, n4 = idx & 15;
    float4 v = *(const float4*)&W[k * (3 * NF) + col0 + n4 * 4];
    v.x = tf32f(v.x); v.y = tf32f(v.y); v.z = tf32f(v.z); v.w = tf32f(v.w);
    *(float4*)&ws[k * WST + n4 * 4] = v;
  }
  __syncthreads();

  float s[8][4];
#pragma unroll
  for (int n = 0; n < 8; ++n)
#pragma unroll
    for (int i = 0; i < 4; ++i) s[n][i] = 0.0f;

  const float* x0 = &xs[(16 * w + tq) * XST];
  const float* x1 = &xs[(16 * w + tq + 8) * XST];

#pragma unroll
  for (int kk = 0; kk < 16; ++kk) {
    float f0 = x0[kk * 8 + tr];
    float f1 = x1[kk * 8 + tr];
    float f2 = x0[kk * 8 + tr + 4];
    float f3 = x1[kk * 8 + tr + 4];
    uint32_t ah[4], al[4];
    ah[0] = f2tf32(f0); ah[1] = f2tf32(f1);
    ah[2] = f2tf32(f2); ah[3] = f2tf32(f3);
    al[0] = f2tf32(f0 - __uint_as_float(ah[0]));
    al[1] = f2tf32(f1 - __uint_as_float(ah[1]));
    al[2] = f2tf32(f2 - __uint_as_float(ah[2]));
    al[3] = f2tf32(f3 - __uint_as_float(ah[3]));
#pragma unroll
    for (int nt = 0; nt < 8; ++nt) {
      uint32_t bb[2];
      const float* wp = &ws[(kk * 8 + tr) * WST + nt * 8 + tq];
      bb[0] = __float_as_uint(wp[0]);
      bb[1] = __float_as_uint(wp[4 * WST]);
      mma_tf32(s[nt], ah, bb);
      mma_tf32(s[nt], al, bb);
    }
  }

  const int sec = blockIdx.y >> 1;          // 0:q 1:k 2:v
  const int wcb = (blockIdx.y & 1) * 64;
  const int npadd = *npadd_p;
  const int r0 = row0 + 16 * w + tq;
  const int r1 = r0 + 8;
  const float qmul = QSCALE * LOG2E;        // exp2-domain logits
#pragma unroll
  for (int nt = 0; nt < 8; ++nt) {
    int c0 = nt * 8 + 2 * tr;
    float b0 = bias[col0 + c0];
    float b1 = bias[col0 + c0 + 1];
    float v00 = s[nt][0] + b0, v01 = s[nt][1] + b1;
    float v10 = s[nt][2] + b0, v11 = s[nt][3] + b1;
    int wc0 = wcb + c0, wc1 = wc0 + 1;
    if (sec == 0) {
      g_Qh[r0 * NF + packc16(wc0)] = __float2bfloat16_rn(v00 * qmul);
      g_Qh[r0 * NF + packc16(wc1)] = __float2bfloat16_rn(v01 * qmul);
      g_Qh[r1 * NF + packc16(wc0)] = __float2bfloat16_rn(v10 * qmul);
      g_Qh[r1 * NF + packc16(wc1)] = __float2bfloat16_rn(v11 * qmul);
    } else if (sec == 1) {
      g_Kh[r0 * NF + packc16(wc0)] = __float2bfloat16_rn(v00);
      g_Kh[r0 * NF + packc16(wc1)] = __float2bfloat16_rn(v01);
      g_Kh[r1 * NF + packc16(wc0)] = __float2bfloat16_rn(v10);
      g_Kh[r1 * NF + packc16(wc1)] = __float2bfloat16_rn(v11);
    } else {
      int pk0 = packc16(r0), pk1 = packc16(r1);
      g_Vh[wc0 * T + pk0] = __float2half_rn((r0 >= npadd) ? v00 : 0.0f);
      g_Vh[wc1 * T + pk0] = __float2half_rn((r0 >= npadd) ? v01 : 0.0f);
      g_Vh[wc0 * T + pk1] = __float2half_rn((r1 >= npadd) ? v10 : 0.0f);
      g_Vh[wc1 * T + pk1] = __float2half_rn((r1 >= npadd) ? v11 : 0.0f);
    }
  }
}

// ---------------------------------------------------------------------------
// Kernel 2: flash attention, bf16 QK + fp16 PV.  Single KV buffer, resident Q,
// 2 CTAs/SM for cross-CTA latency hiding.  Warp w owns rows 16w..16w+15.
// ---------------------------------------------------------------------------
__global__ void __launch_bounds__(256, 2) attn_kernel(const int* __restrict__ npadd_p) {
  extern __shared__ char smc[];

  const int tid = threadIdx.x;
  const int lane = tid & 31;
  const int w = tid >> 5;
  const int tq = lane >> 2;
  const int tr = lane & 3;

  const int qt = 63 - blockIdx.x;
  const int ch = blockIdx.y;
  const int kcount = 2 * (qt + 1);
  const int nch = (kcount + NKT - 1) / NKT;
  if (ch >= nch) return;
  const int k0 = ch * NKT;
  const int k1 = (k0 + NKT < kcount) ? (k0 + NKT) : kcount;
  const int npadd = *npadd_p;
  const int qrow0 = qt * BM;

  const uint32_t sb = smem_u32(smc);

  // ---- prologue: fetch Q (resident) + first K/V tile ----
  {
    const char* qsrc = (const char*)g_Qh + (size_t)qrow0 * (NF * 2);
#pragma unroll
    for (int it = 0; it < 8; ++it) {
      int idx = tid + it * 256;
      int r = idx >> 4, seg = idx & 15;
      cp16(sb + QS_OFF + r * QSTB + seg * 16, qsrc + r * (NF * 2) + seg * 16);
    }
    const int kbase = k0 * BN;
    const char* ksrc = (const char*)g_Kh + (size_t)kbase * (NF * 2);
#pragma unroll
    for (int it = 0; it < 4; ++it) {
      int idx = tid + it * 256;
      int r = idx >> 4, seg = idx & 15;
      cp16(sb + r * KSTB + seg * 16, ksrc + r * (NF * 2) + seg * 16);
    }
    const char* vsrc = (const char*)g_Vh + (size_t)kbase * 2;
#pragma unroll
    for (int it = 0; it < 4; ++it) {
      int idx = tid + it * 256;
      int r = idx >> 3, seg = idx & 7;
      cp16(sb + K_TILE + r * VSTB + seg * 16, vsrc + (size_t)r * (T * 2) + seg * 16);
    }
    asm volatile("cp.async.commit_group;" ::: "memory");
    asm volatile("cp.async.wait_group 0;" ::: "memory");
  }
  __syncthreads();

  const int r0g = qrow0 + 16 * w + tq;
  const int r1g = r0g + 8;
  float m0 = neg_inf(), m1 = neg_inf(), l0s = 0.0f, l1s = 0.0f;
  float o[16][4];
#pragma unroll
  for (int n = 0; n < 16; ++n)
#pragma unroll
    for (int i = 0; i < 4; ++i) o[n][i] = 0.0f;

  char* pw = smc + PS_OFF + w * 16 * PSTB;
  const char* q0p = smc + QS_OFF + (16 * w + tq) * QSTB + tr * 8;
  const char* Ks = smc;
  const char* Vs = smc + K_TILE;

  for (int kt = k0; kt < k1; ++kt) {
    const int kbase = kt * BN;

    // ---- S = Q @ K^T : 8 kk(16) x 8 nt; Q frags reloaded from smem ----
    float s[8][4];
#pragma unroll
    for (int n = 0; n < 8; ++n)
#pragma unroll
      for (int i = 0; i < 4; ++i) s[n][i] = 0.0f;

#pragma unroll
    for (int kk = 0; kk < 8; ++kk) {
      uint2 l0 = *(const uint2*)(q0p + kk * 32);
      uint2 l1 = *(const uint2*)(q0p + 8 * QSTB + kk * 32);
      uint32_t qa[4] = {l0.x, l1.x, l0.y, l1.y};
#pragma unroll
      for (int nt = 0; nt < 8; ++nt) {
        uint2 bb = *(const uint2*)(Ks + (nt * 8 + tq) * KSTB + kk * 32 + tr * 8);
        mma_bf16(s[nt], qa, (const uint32_t*)&bb);
      }
    }

    // ---- mask ----
    const bool needmask = (kbase + BN > qrow0) || (kbase < npadd) || (qrow0 < npadd);
    if (needmask) {
#pragma unroll
      for (int nt = 0; nt < 8; ++nt) {
        int j0 = kbase + nt * 8 + 2 * tr;
        int j1 = j0 + 1;
        if (j0 > r0g || j0 < npadd || r0g < npadd) s[nt][0] = neg_inf();
        if (j1 > r0g || j1 < npadd || r0g < npadd) s[nt][1] = neg_inf();
        if (j0 > r1g || j0 < npadd || r1g < npadd) s[nt][2] = neg_inf();
        if (j1 > r1g || j1 < npadd || r1g < npadd) s[nt][3] = neg_inf();
      }
    }

    // ---- warp-local online softmax (exp2 domain) ----
    float mx0 = neg_inf(), mx1 = neg_inf();
#pragma unroll
    for (int nt = 0; nt < 8; ++nt) {
      mx0 = fmaxf(mx0, fmaxf(s[nt][0], s[nt][1]));
      mx1 = fmaxf(mx1, fmaxf(s[nt][2], s[nt][3]));
    }
    mx0 = fmaxf(mx0, __shfl_xor_sync(0xffffffffu, mx0, 1));
    mx0 = fmaxf(mx0, __shfl_xor_sync(0xffffffffu, mx0, 2));
    mx1 = fmaxf(mx1, __shfl_xor_sync(0xffffffffu, mx1, 1));
    mx1 = fmaxf(mx1, __shfl_xor_sync(0xffffffffu, mx1, 2));

    float mn0 = fmaxf(m0, mx0);
    float mn1 = fmaxf(m1, mx1);
    float a0 = (mn0 == neg_inf()) ? 1.0f : exp2f(m0 - mn0);
    float a1 = (mn1 == neg_inf()) ? 1.0f : exp2f(m1 - mn1);
    m0 = mn0; m1 = mn1;
    const bool dead0 = (mn0 == neg_inf());
    const bool dead1 = (mn1 == neg_inf());

    // rescale O only if needed anywhere in the warp (skipped ~80% of tiles)
    if (kt > k0 && __any_sync(0xffffffffu, (a0 != 1.0f) | (a1 != 1.0f))) {
#pragma unroll
      for (int n = 0; n < 16; ++n) {
        o[n][0] *= a0; o[n][1] *= a0;
        o[n][2] *= a1; o[n][3] *= a1;
      }
    }

    float sum0 = 0.0f, sum1 = 0.0f;
#pragma unroll
    for (int nth = 0; nth < 4; ++nth) {   // nt pairs -> STS.64
      float p00, p01, p02, p03, p10, p11, p12, p13;
      {
        int nt = 2 * nth;
        p00 = dead0 ? 0.0f : exp2f(s[nt][0] - mn0);
        p01 = dead0 ? 0.0f : exp2f(s[nt][1] - mn0);
        p10 = dead1 ? 0.0f : exp2f(s[nt][2] - mn1);
        p11 = dead1 ? 0.0f : exp2f(s[nt][3] - mn1);
        p02 = dead0 ? 0.0f : exp2f(s[nt + 1][0] - mn0);
        p03 = dead0 ? 0.0f : exp2f(s[nt + 1][1] - mn0);
        p12 = dead1 ? 0.0f : exp2f(s[nt + 1][2] - mn1);
        p13 = dead1 ? 0.0f : exp2f(s[nt + 1][3] - mn1);
      }
      sum0 += (p00 + p01) + (p02 + p03);
      sum1 += (p10 + p11) + (p12 + p13);
      uint2 st0, st1;
      *(__half2*)&st0.x = __floats2half2_rn(p00, p01);
      *(__half2*)&st0.y = __floats2half2_rn(p02, p03);
      *(__half2*)&st1.x = __floats2half2_rn(p10, p11);
      *(__half2*)&st1.y = __floats2half2_rn(p12, p13);
      int off = nth * 32 + tr * 8;
      *(uint2*)(pw + tq * PSTB + off) = st0;
      *(uint2*)(pw + (tq + 8) * PSTB + off) = st1;
    }
    sum0 += __shfl_xor_sync(0xffffffffu, sum0, 1);
    sum0 += __shfl_xor_sync(0xffffffffu, sum0, 2);
    sum1 += __shfl_xor_sync(0xffffffffu, sum1, 1);
    sum1 += __shfl_xor_sync(0xffffffffu, sum1, 2);
    l0s = l0s * a0 + sum0;
    l1s = l1s * a1 + sum1;
    __syncwarp();

    // ---- O += P @ V ----
#pragma unroll
    for (int ktk = 0; ktk < 4; ++ktk) {
      uint2 p0 = *(const uint2*)(pw + tq * PSTB + ktk * 32 + tr * 8);
      uint2 p1 = *(const uint2*)(pw + (tq + 8) * PSTB + ktk * 32 + tr * 8);
      uint32_t pa[4] = {p0.x, p1.x, p0.y, p1.y};
#pragma unroll
      for (int nt2 = 0; nt2 < 16; ++nt2) {
        uint2 bb = *(const uint2*)(Vs + (nt2 * 8 + tq) * VSTB + ktk * 32 + tr * 8);
        mma_f16(o[nt2], pa, (const uint32_t*)&bb);
      }
    }

    // ---- fetch next tile into the (single) buffer ----
    if (kt + 1 < k1) {
      __syncthreads();   // everyone done reading Ks/Vs
      const int nb = (kt + 1) * BN;
      const char* ksrc = (const char*)g_Kh + (size_t)nb * (NF * 2);
#pragma unroll
      for (int it = 0; it < 4; ++it) {
        int idx = tid + it * 256;
        int r = idx >> 4, seg = idx & 15;
        cp16(sb + r * KSTB + seg * 16, ksrc + r * (NF * 2) + seg * 16);
      }
      const char* vsrc = (const char*)g_Vh + (size_t)nb * 2;
#pragma unroll
      for (int it = 0; it < 4; ++it) {
        int idx = tid + it * 256;
        int r = idx >> 3, seg = idx & 7;
        cp16(sb + K_TILE + r * VSTB + seg * 16, vsrc + (size_t)r * (T * 2) + seg * 16);
      }
      asm volatile("cp.async.commit_group;" ::: "memory");
      asm volatile("cp.async.wait_group 0;" ::: "memory");
      __syncthreads();
    }
  }

  // ---- write split partials (unnormalized) ----
  float* ob0 = &g_O[((size_t)ch * T + r0g) * NF];
  float* ob1 = &g_O[((size_t)ch * T + r1g) * NF];
#pragma unroll
  for (int nt2 = 0; nt2 < 16; ++nt2) {
    int c = nt2 * 8 + 2 * tr;
    *(float2*)&ob0[c] = make_float2(o[nt2][0], o[nt2][1]);
    *(float2*)&ob1[c] = make_float2(o[nt2][2], o[nt2][3]);
  }
  if (tr == 0) {
    g_M[ch * T + r0g] = m0; g_M[ch * T + r1g] = m1;
    g_L[ch * T + r0g] = l0s; g_L[ch * T + r1g] = l1s;
  }
}

// ---------------------------------------------------------------------------
// Kernel 3: combine split partials (exp2-domain m).
// ---------------------------------------------------------------------------
__global__ void __launch_bounds__(256) combine_kernel(float* __restrict__ out) {
  const int tid = threadIdx.x;
  const int t = blockIdx.x * 2 + (tid >> 7);
  const int c = tid & 127;
  const int qt = t >> 7;
  const int nch = (qt + 8) / 8;

  float m[NSPLIT_MAX], l[NSPLIT_MAX];
  float mx = neg_inf();
  for (int s = 0; s < nch; ++s) {
    m[s] = g_M[s * T + t];
    l[s] = g_L[s * T + t];
    mx = fmaxf(mx, m[s]);
  }
  if (mx == neg_inf()) { out[t * NF + c] = 0.0f; return; }
  float den = 0.0f, num = 0.0f;
  for (int s = 0; s < nch; ++s) {
    float wgt = (m[s] == neg_inf()) ? 0.0f : exp2f(m[s] - mx);
    den += wgt * l[s];
    num = fmaf(wgt, g_O[((size_t)s * T + t) * NF + c], num);
  }
  out[t * NF + c] = num / den;
}

// ---------------------------------------------------------------------------
extern "C" void kernel_launch(void* const* d_in, const int* in_sizes, int n_in,
                              void* d_out, int out_size) {
  const float* x = (const float*)d_in[0];
  const float* W = (const float*)d_in[1];
  const float* b = (const float*)d_in[2];
  const int* npadd = (const int*)d_in[3];
  float* out = (float*)d_out;

  constexpr int PROJ_SMEM = (128 * XST + 128 * WST) * (int)sizeof(float);  // ~102KB
  cudaFuncSetAttribute(proj_kernel, cudaFuncAttributeMaxDynamicSharedMemorySize, PROJ_SMEM);
  cudaFuncSetAttribute(attn_kernel, cudaFuncAttributeMaxDynamicSharedMemorySize, ATTN_SMEM);

  proj_kernel<<<dim3(64, 6), 256, PROJ_SMEM>>>(x, W, b, npadd);
  attn_kernel<<<dim3(64, NSPLIT_MAX), 256, ATTN_SMEM>>>(npadd);
  combine_kernel<<<T / 2, 256>>>(out);
}

// round 7
// speedup vs baseline: 5.2773x; 1.0029x over previous
#include <cuda_runtime.h>
#include <cuda_fp16.h>
#include <cuda_bf16.h>
#include <cstdint>

// Problem constants
#define T      8192
#define NF     128
#define CINP   128
#define LOG2E  1.4426950408889634f
#define QSCALE 0.08838834764831845f  // 1/sqrt(128)
#define NSPLIT_MAX 8

// Attention tiling
#define BM 128
#define BN 64
#define NKT 16
#define KSTB 288
#define VSTB 160
#define PSTB 160
#define QSTB 288

// smem layout (bytes) — single KV buffer, resident Q  => 2 CTAs/SM
#define K_TILE  (64 * KSTB)          // 18432
#define V_TILE  (128 * VSTB)         // 20480
#define KV_BUF  (K_TILE + V_TILE)    // 38912
#define PS_OFF  KV_BUF
#define PS_SIZE (8 * 16 * PSTB)      // 20480
#define QS_OFF  (PS_OFF + PS_SIZE)
#define QS_SIZE (128 * QSTB)         // 36864
#define ATTN_SMEM (QS_OFF + QS_SIZE) // 96256

// Scratch.  Packed fragment-order operand tensors.
__device__ __nv_bfloat16 g_Qh[T * NF];   // [row][packc16(d)], scaled QSCALE*log2e
__device__ __nv_bfloat16 g_Kh[T * NF];   // [key][packc16(d)]
__device__ __half        g_Vh[NF * T];   // [d][packc16(key)]
__device__ float g_O[NSPLIT_MAX * T * NF];
__device__ float g_M[NSPLIT_MAX * T];
__device__ float g_L[NSPLIT_MAX * T];

__device__ __forceinline__ float neg_inf() { return __int_as_float(0xff800000u); }

__device__ __forceinline__ uint32_t f2tf32(float f) {
  uint32_t u;
  asm("cvt.rna.tf32.f32 %0, %1;" : "=r"(u) : "f"(f));
  return u;
}
__device__ __forceinline__ float tf32f(float f) {
  return __uint_as_float(f2tf32(f));
}

// fragment-order permutation within each 16-group
__device__ __forceinline__ int packc16(int c) {
  int u = c & 7, pr = (c >> 3) & 1;
  return (c & ~15) | (((u >> 1) << 2) | (u & 1) | (pr << 1));
}

__device__ __forceinline__ void mma_tf32(float* d, const uint32_t* a,
                                         const uint32_t* b) {
  asm volatile(
      "mma.sync.aligned.m16n8k8.row.col.f32.tf32.tf32.f32 "
      "{%0,%1,%2,%3}, {%4,%5,%6,%7}, {%8,%9}, {%0,%1,%2,%3};\n"
      : "+f"(d[0]), "+f"(d[1]), "+f"(d[2]), "+f"(d[3])
      : "r"(a[0]), "r"(a[1]), "r"(a[2]), "r"(a[3]), "r"(b[0]), "r"(b[1]));
}
__device__ __forceinline__ void mma_bf16(float* d, const uint32_t* a,
                                         const uint32_t* b) {
  asm volatile(
      "mma.sync.aligned.m16n8k16.row.col.f32.bf16.bf16.f32 "
      "{%0,%1,%2,%3}, {%4,%5,%6,%7}, {%8,%9}, {%0,%1,%2,%3};\n"
      : "+f"(d[0]), "+f"(d[1]), "+f"(d[2]), "+f"(d[3])
      : "r"(a[0]), "r"(a[1]), "r"(a[2]), "r"(a[3]), "r"(b[0]), "r"(b[1]));
}
__device__ __forceinline__ void mma_f16(float* d, const uint32_t* a,
                                        const uint32_t* b) {
  asm volatile(
      "mma.sync.aligned.m16n8k16.row.col.f32.f16.f16.f32 "
      "{%0,%1,%2,%3}, {%4,%5,%6,%7}, {%8,%9}, {%0,%1,%2,%3};\n"
      : "+f"(d[0]), "+f"(d[1]), "+f"(d[2]), "+f"(d[3])
      : "r"(a[0]), "r"(a[1]), "r"(a[2]), "r"(a[3]), "r"(b[0]), "r"(b[1]));
}

__device__ __forceinline__ uint32_t smem_u32(const void* p) {
  uint32_t a;
  asm("{ .reg .u64 t; cvta.to.shared.u64 t, %1; cvt.u32.u64 %0, t; }"
      : "=r"(a) : "l"(p));
  return a;
}
__device__ __forceinline__ void cp16(uint32_t daddr, const void* src) {
  asm volatile("cp.async.cg.shared.global [%0], [%1], 16;"
               :: "r"(daddr), "l"(src));
}
#define CP_COMMIT() asm volatile("cp.async.commit_group;" ::: "memory")
#define CP_WAIT1()  asm volatile("cp.async.wait_group 1;" ::: "memory")
#define CP_WAIT0()  asm volatile("cp.async.wait_group 0;" ::: "memory")

// ---------------------------------------------------------------------------
// Kernel 1: QKV projection via mma.sync tf32, 2-term split.
// W in smem packed as k-pairs (k, k+4) adjacent -> one LDS.64 per B-frag.
// Epilogue: stage 16KB result tile in smem (reusing xs), flush coalesced.
// ---------------------------------------------------------------------------
#define XST 132
#define WST2 136   // floats per packed-W row (64 rows of 64 pairs + pad)
__global__ void __launch_bounds__(256, 2) proj_kernel(
    const float* __restrict__ x, const float* __restrict__ W,
    const float* __restrict__ bias, const int* __restrict__ npadd_p) {
  extern __shared__ float sm[];
  float* xs = sm;                 // [128][XST] fp32 (reused as output staging)
  float* ws = sm + 128 * XST;     // packed W: [64][WST2]

  const int tid = threadIdx.x;
  const int lane = tid & 31;
  const int w = tid >> 5;
  const int tq = lane >> 2;
  const int tr = lane & 3;
  const int row0 = blockIdx.x * 128;
  const int col0 = blockIdx.y * 64;

#pragma unroll
  for (int it = 0; it < 16; ++it) {
    int idx = tid + it * 256;
    int r = idx >> 5, c4 = idx & 31;
    *(float4*)&xs[r * XST + c4 * 4] =
        *(const float4*)&x[(row0 + r) * CINP + c4 * 4];
  }
#pragma unroll
  for (int it = 0; it < 8; ++it) {
    int idx = tid + it * 256;
    int k = idx >> 4, n4 = idx & 15;
    float4 v = *(const float4*)&W[k * (3 * NF) + col0 + n4 * 4];
    int kp = ((k & 3) + ((k >> 3) << 2)) * WST2 + ((k >> 2) & 1);
    ws[kp + (n4 * 4 + 0) * 2] = tf32f(v.x);
    ws[kp + (n4 * 4 + 1) * 2] = tf32f(v.y);
    ws[kp + (n4 * 4 + 2) * 2] = tf32f(v.z);
    ws[kp + (n4 * 4 + 3) * 2] = tf32f(v.w);
  }
  __syncthreads();

  float s[8][4];
#pragma unroll
  for (int n = 0; n < 8; ++n)
#pragma unroll
    for (int i = 0; i < 4; ++i) s[n][i] = 0.0f;

  const float* x0 = &xs[(16 * w + tq) * XST];
  const float* x1 = &xs[(16 * w + tq + 8) * XST];

#pragma unroll
  for (int kk = 0; kk < 16; ++kk) {
    float f0 = x0[kk * 8 + tr];
    float f1 = x1[kk * 8 + tr];
    float f2 = x0[kk * 8 + tr + 4];
    float f3 = x1[kk * 8 + tr + 4];
    uint32_t ah[4], al[4];
    ah[0] = f2tf32(f0); ah[1] = f2tf32(f1);
    ah[2] = f2tf32(f2); ah[3] = f2tf32(f3);
    al[0] = f2tf32(f0 - __uint_as_float(ah[0]));
    al[1] = f2tf32(f1 - __uint_as_float(ah[1]));
    al[2] = f2tf32(f2 - __uint_as_float(ah[2]));
    al[3] = f2tf32(f3 - __uint_as_float(ah[3]));
    const float* wrow = &ws[(kk * 4 + tr) * WST2];
#pragma unroll
    for (int nt = 0; nt < 8; ++nt) {
      float2 wv = *(const float2*)&wrow[(nt * 8 + tq) * 2];
      uint32_t bb[2] = {__float_as_uint(wv.x), __float_as_uint(wv.y)};
      mma_tf32(s[nt], ah, bb);
      mma_tf32(s[nt], al, bb);
    }
  }

  const int sec = blockIdx.y >> 1;          // 0:q 1:k 2:v
  const int wcb = (blockIdx.y & 1) * 64;
  const int npadd = *npadd_p;
  const int lr0 = 16 * w + tq;
  const int lr1 = lr0 + 8;
  const float qmul = QSCALE * LOG2E;

  __syncthreads();                // done reading xs/ws; reuse xs as staging
  char* stg = (char*)sm;

  if (sec < 2) {
    const float scale = (sec == 0) ? qmul : 1.0f;
#pragma unroll
    for (int nt = 0; nt < 8; ++nt) {
      int c0 = nt * 8 + 2 * tr, c1 = c0 + 1;
      float b0 = bias[col0 + c0], b1 = bias[col0 + c1];
      *(__nv_bfloat16*)(stg + lr0 * 144 + packc16(c0) * 2) =
          __float2bfloat16_rn((s[nt][0] + b0) * scale);
      *(__nv_bfloat16*)(stg + lr0 * 144 + packc16(c1) * 2) =
          __float2bfloat16_rn((s[nt][1] + b1) * scale);
      *(__nv_bfloat16*)(stg + lr1 * 144 + packc16(c0) * 2) =
          __float2bfloat16_rn((s[nt][2] + b0) * scale);
      *(__nv_bfloat16*)(stg + lr1 * 144 + packc16(c1) * 2) =
          __float2bfloat16_rn((s[nt][3] + b1) * scale);
    }
  } else {
    const bool z0 = (row0 + lr0) < npadd;
    const bool z1 = (row0 + lr1) < npadd;
    const int pk0 = packc16(lr0) * 2, pk1 = packc16(lr1) * 2;
#pragma unroll
    for (int nt = 0; nt < 8; ++nt) {
      int c0 = nt * 8 + 2 * tr, c1 = c0 + 1;
      float b0 = bias[col0 + c0], b1 = bias[col0 + c1];
      *(__half*)(stg + c0 * 272 + pk0) = __float2half_rn(z0 ? 0.0f : s[nt][0] + b0);
      *(__half*)(stg + c1 * 272 + pk0) = __float2half_rn(z0 ? 0.0f : s[nt][1] + b1);
      *(__half*)(stg + c0 * 272 + pk1) = __float2half_rn(z1 ? 0.0f : s[nt][2] + b0);
      *(__half*)(stg + c1 * 272 + pk1) = __float2half_rn(z1 ? 0.0f : s[nt][3] + b1);
    }
  }
  __syncthreads();

  if (sec < 2) {
    char* gd = (char*)((sec == 0) ? g_Qh : g_Kh);
#pragma unroll
    for (int it = 0; it < 4; ++it) {
      int idx = tid + it * 256;
      int r = idx >> 3, seg = idx & 7;
      *(float4*)(gd + (size_t)(row0 + r) * 256 + wcb * 2 + seg * 16) =
          *(const float4*)(stg + r * 144 + seg * 16);
    }
  } else {
    char* gd = (char*)g_Vh;
#pragma unroll
    for (int it = 0; it < 4; ++it) {
      int idx = tid + it * 256;
      int d = idx >> 4, seg = idx & 15;
      *(float4*)(gd + ((size_t)(wcb + d) * T + row0) * 2 + seg * 16) =
          *(const float4*)(stg + d * 272 + seg * 16);
    }
  }
}

// ---------------------------------------------------------------------------
// Kernel 2: flash attention, bf16 QK + fp16 PV.  Single KV buffers with
// time-sliced cp.async prefetch (K after QK, V after PV), 2 CTAs/SM.
// ---------------------------------------------------------------------------
__global__ void __launch_bounds__(256, 2) attn_kernel(const int* __restrict__ npadd_p) {
  extern __shared__ char smc[];

  const int tid = threadIdx.x;
  const int lane = tid & 31;
  const int w = tid >> 5;
  const int tq = lane >> 2;
  const int tr = lane & 3;

  const int qt = 63 - blockIdx.x;
  const int ch = blockIdx.y;
  const int kcount = 2 * (qt + 1);
  const int nch = (kcount + NKT - 1) / NKT;
  if (ch >= nch) return;
  const int k0 = ch * NKT;
  const int k1 = (k0 + NKT < kcount) ? (k0 + NKT) : kcount;
  const int npadd = *npadd_p;
  const int qrow0 = qt * BM;

  const uint32_t sb = smem_u32(smc);

  // ---- prologue: fetch Q + first K/V tile (one group) ----
  {
    const char* qsrc = (const char*)g_Qh + (size_t)qrow0 * (NF * 2);
#pragma unroll
    for (int it = 0; it < 8; ++it) {
      int idx = tid + it * 256;
      int r = idx >> 4, seg = idx & 15;
      cp16(sb + QS_OFF + r * QSTB + seg * 16, qsrc + r * (NF * 2) + seg * 16);
    }
    const int kbase = k0 * BN;
    const char* ksrc = (const char*)g_Kh + (size_t)kbase * (NF * 2);
#pragma unroll
    for (int it = 0; it < 4; ++it) {
      int idx = tid + it * 256;
      int r = idx >> 4, seg = idx & 15;
      cp16(sb + r * KSTB + seg * 16, ksrc + r * (NF * 2) + seg * 16);
    }
    const char* vsrc = (const char*)g_Vh + (size_t)kbase * 2;
#pragma unroll
    for (int it = 0; it < 4; ++it) {
      int idx = tid + it * 256;
      int r = idx >> 3, seg = idx & 7;
      cp16(sb + K_TILE + r * VSTB + seg * 16, vsrc + (size_t)r * (T * 2) + seg * 16);
    }
    CP_COMMIT();
    CP_WAIT0();
  }
  __syncthreads();

  const int r0g = qrow0 + 16 * w + tq;
  const int r1g = r0g + 8;
  float m0 = neg_inf(), m1 = neg_inf(), l0s = 0.0f, l1s = 0.0f;
  float o[16][4];
#pragma unroll
  for (int n = 0; n < 16; ++n)
#pragma unroll
    for (int i = 0; i < 4; ++i) o[n][i] = 0.0f;

  char* pw = smc + PS_OFF + w * 16 * PSTB;
  const char* q0p = smc + QS_OFF + (16 * w + tq) * QSTB + tr * 8;
  const char* Ks = smc;
  const char* Vs = smc + K_TILE;

  for (int kt = k0; kt < k1; ++kt) {
    const int kbase = kt * BN;

    // ---- S = Q @ K^T ----
    float s[8][4];
#pragma unroll
    for (int n = 0; n < 8; ++n)
#pragma unroll
      for (int i = 0; i < 4; ++i) s[n][i] = 0.0f;

#pragma unroll
    for (int kk = 0; kk < 8; ++kk) {
      uint2 l0 = *(const uint2*)(q0p + kk * 32);
      uint2 l1 = *(const uint2*)(q0p + 8 * QSTB + kk * 32);
      uint32_t qa[4] = {l0.x, l1.x, l0.y, l1.y};
#pragma unroll
      for (int nt = 0; nt < 8; ++nt) {
        uint2 bb = *(const uint2*)(Ks + (nt * 8 + tq) * KSTB + kk * 32 + tr * 8);
        mma_bf16(s[nt], qa, (const uint32_t*)&bb);
      }
    }
    __syncthreads();                       // all warps done reading Ks

    // ---- prefetch K(t+1) into the (now free) K buffer ----
    if (kt + 1 < k1) {
      const char* ksrc = (const char*)g_Kh + (size_t)(kt + 1) * BN * (NF * 2);
#pragma unroll
      for (int it = 0; it < 4; ++it) {
        int idx = tid + it * 256;
        int r = idx >> 4, seg = idx & 15;
        cp16(sb + r * KSTB + seg * 16, ksrc + r * (NF * 2) + seg * 16);
      }
    }
    CP_COMMIT();                           // K group (possibly empty)

    // ---- mask ----
    const bool needmask = (kbase + BN > qrow0) || (kbase < npadd) || (qrow0 < npadd);
    if (needmask) {
#pragma unroll
      for (int nt = 0; nt < 8; ++nt) {
        int j0 = kbase + nt * 8 + 2 * tr;
        int j1 = j0 + 1;
        if (j0 > r0g || j0 < npadd || r0g < npadd) s[nt][0] = neg_inf();
        if (j1 > r0g || j1 < npadd || r0g < npadd) s[nt][1] = neg_inf();
        if (j0 > r1g || j0 < npadd || r1g < npadd) s[nt][2] = neg_inf();
        if (j1 > r1g || j1 < npadd || r1g < npadd) s[nt][3] = neg_inf();
      }
    }

    // ---- warp-local online softmax (exp2 domain) ----
    float mx0 = neg_inf(), mx1 = neg_inf();
#pragma unroll
    for (int nt = 0; nt < 8; ++nt) {
      mx0 = fmaxf(mx0, fmaxf(s[nt][0], s[nt][1]));
      mx1 = fmaxf(mx1, fmaxf(s[nt][2], s[nt][3]));
    }
    mx0 = fmaxf(mx0, __shfl_xor_sync(0xffffffffu, mx0, 1));
    mx0 = fmaxf(mx0, __shfl_xor_sync(0xffffffffu, mx0, 2));
    mx1 = fmaxf(mx1, __shfl_xor_sync(0xffffffffu, mx1, 1));
    mx1 = fmaxf(mx1, __shfl_xor_sync(0xffffffffu, mx1, 2));

    float mn0 = fmaxf(m0, mx0);
    float mn1 = fmaxf(m1, mx1);
    float a0 = (mn0 == neg_inf()) ? 1.0f : exp2f(m0 - mn0);
    float a1 = (mn1 == neg_inf()) ? 1.0f : exp2f(m1 - mn1);
    m0 = mn0; m1 = mn1;
    const bool dead0 = (mn0 == neg_inf());
    const bool dead1 = (mn1 == neg_inf());

    if (kt > k0 && __any_sync(0xffffffffu, (a0 != 1.0f) | (a1 != 1.0f))) {
#pragma unroll
      for (int n = 0; n < 16; ++n) {
        o[n][0] *= a0; o[n][1] *= a0;
        o[n][2] *= a1; o[n][3] *= a1;
      }
    }

    float sum0 = 0.0f, sum1 = 0.0f;
#pragma unroll
    for (int nth = 0; nth < 4; ++nth) {
      float p00, p01, p02, p03, p10, p11, p12, p13;
      {
        int nt = 2 * nth;
        p00 = dead0 ? 0.0f : exp2f(s[nt][0] - mn0);
        p01 = dead0 ? 0.0f : exp2f(s[nt][1] - mn0);
        p10 = dead1 ? 0.0f : exp2f(s[nt][2] - mn1);
        p11 = dead1 ? 0.0f : exp2f(s[nt][3] - mn1);
        p02 = dead0 ? 0.0f : exp2f(s[nt + 1][0] - mn0);
        p03 = dead0 ? 0.0f : exp2f(s[nt + 1][1] - mn0);
        p12 = dead1 ? 0.0f : exp2f(s[nt + 1][2] - mn1);
        p13 = dead1 ? 0.0f : exp2f(s[nt + 1][3] - mn1);
      }
      sum0 += (p00 + p01) + (p02 + p03);
      sum1 += (p10 + p11) + (p12 + p13);
      uint2 st0, st1;
      *(__half2*)&st0.x = __floats2half2_rn(p00, p01);
      *(__half2*)&st0.y = __floats2half2_rn(p02, p03);
      *(__half2*)&st1.x = __floats2half2_rn(p10, p11);
      *(__half2*)&st1.y = __floats2half2_rn(p12, p13);
      int off = nth * 32 + tr * 8;
      *(uint2*)(pw + tq * PSTB + off) = st0;
      *(uint2*)(pw + (tq + 8) * PSTB + off) = st1;
    }
    sum0 += __shfl_xor_sync(0xffffffffu, sum0, 1);
    sum0 += __shfl_xor_sync(0xffffffffu, sum0, 2);
    sum1 += __shfl_xor_sync(0xffffffffu, sum1, 1);
    sum1 += __shfl_xor_sync(0xffffffffu, sum1, 2);
    l0s = l0s * a0 + sum0;
    l1s = l1s * a1 + sum1;

    CP_WAIT1();                            // V(t) complete (FIFO: older than K(t+1))
    __syncthreads();                       // V visible to all warps

    // ---- O += P @ V ----
#pragma unroll
    for (int ktk = 0; ktk < 4; ++ktk) {
      uint2 p0 = *(const uint2*)(pw + tq * PSTB + ktk * 32 + tr * 8);
      uint2 p1 = *(const uint2*)(pw + (tq + 8) * PSTB + ktk * 32 + tr * 8);
      uint32_t pa[4] = {p0.x, p1.x, p0.y, p1.y};
#pragma unroll
      for (int nt2 = 0; nt2 < 16; ++nt2) {
        uint2 bb = *(const uint2*)(Vs + (nt2 * 8 + tq) * VSTB + ktk * 32 + tr * 8);
        mma_f16(o[nt2], pa, (const uint32_t*)&bb);
      }
    }
    __syncthreads();                       // all warps done reading Vs

    // ---- prefetch V(t+1) ----
    if (kt + 1 < k1) {
      const char* vsrc = (const char*)g_Vh + (size_t)(kt + 1) * BN * 2;
#pragma unroll
      for (int it = 0; it < 4; ++it) {
        int idx = tid + it * 256;
        int r = idx >> 3, seg = idx & 7;
        cp16(sb + K_TILE + r * VSTB + seg * 16, vsrc + (size_t)r * (T * 2) + seg * 16);
      }
    }
    CP_COMMIT();                           // V group (possibly empty)
    CP_WAIT1();                            // K(t+1) complete
    __syncthreads();                       // K visible
  }

  // ---- write split partials ----
  float* ob0 = &g_O[((size_t)ch * T + r0g) * NF];
  float* ob1 = &g_O[((size_t)ch * T + r1g) * NF];
#pragma unroll
  for (int nt2 = 0; nt2 < 16; ++nt2) {
    int c = nt2 * 8 + 2 * tr;
    *(float2*)&ob0[c] = make_float2(o[nt2][0], o[nt2][1]);
    *(float2*)&ob1[c] = make_float2(o[nt2][2], o[nt2][3]);
  }
  if (tr == 0) {
    g_M[ch * T + r0g] = m0; g_M[ch * T + r1g] = m1;
    g_L[ch * T + r0g] = l0s; g_L[ch * T + r1g] = l1s;
  }
}

// ---------------------------------------------------------------------------
// Kernel 3: combine split partials (exp2-domain m).
// ---------------------------------------------------------------------------
__global__ void __launch_bounds__(256) combine_kernel(float* __restrict__ out) {
  const int tid = threadIdx.x;
  const int t = blockIdx.x * 2 + (tid >> 7);
  const int c = tid & 127;
  const int qt = t >> 7;
  const int nch = (qt + 8) / 8;

  float m[NSPLIT_MAX], l[NSPLIT_MAX];
  float mx = neg_inf();
  for (int s = 0; s < nch; ++s) {
    m[s] = g_M[s * T + t];
    l[s] = g_L[s * T + t];
    mx = fmaxf(mx, m[s]);
  }
  if (mx == neg_inf()) { out[t * NF + c] = 0.0f; return; }
  float den = 0.0f, num = 0.0f;
  for (int s = 0; s < nch; ++s) {
    float wgt = (m[s] == neg_inf()) ? 0.0f : exp2f(m[s] - mx);
    den += wgt * l[s];
    num = fmaf(wgt, g_O[((size_t)s * T + t) * NF + c], num);
  }
  out[t * NF + c] = num / den;
}

// ---------------------------------------------------------------------------
extern "C" void kernel_launch(void* const* d_in, const int* in_sizes, int n_in,
                              void* d_out, int out_size) {
  const float* x = (const float*)d_in[0];
  const float* W = (const float*)d_in[1];
  const float* b = (const float*)d_in[2];
  const int* npadd = (const int*)d_in[3];
  float* out = (float*)d_out;

  constexpr int PROJ_SMEM = (128 * XST + 64 * WST2) * (int)sizeof(float);  // 100KB
  cudaFuncSetAttribute(proj_kernel, cudaFuncAttributeMaxDynamicSharedMemorySize, PROJ_SMEM);
  cudaFuncSetAttribute(attn_kernel, cudaFuncAttributeMaxDynamicSharedMemorySize, ATTN_SMEM);

  proj_kernel<<<dim3(64, 6), 256, PROJ_SMEM>>>(x, W, b, npadd);
  attn_kernel<<<dim3(64, NSPLIT_MAX), 256, ATTN_SMEM>>>(npadd);
  combine_kernel<<<T / 2, 256>>>(out);
}